// round 1
// baseline (speedup 1.0000x reference)
#include <cuda_runtime.h>
#include <math.h>

#define Bsz 2048
#define Kk 128
#define Mm 640
#define HWS 132          // padded HW row stride (floats), 16B aligned
#define NTHREADS 256

// ---- shared memory layout (float offsets) ----
#define OFF_HW    0                    // 128*132 = 16896
#define OFF_XS    (OFF_HW + 128*HWS)   // 640
#define OFF_SX1   (OFF_XS + 640)       // 640
#define OFF_Z1    (OFF_SX1 + 640)      // 4096  (reused as U0)
#define OFF_W64   (OFF_Z1 + 4096)      // 8192  (reused: V @ +0, Z2 @ +4096)
#define OFF_T     (OFF_W64 + 8192)     // 8192  (reused as SZ2)
#define OFF_SW    (OFF_T + 8192)       // 1088 small weights
#define OFF_C     (OFF_SW + 1088)      // 128 column means of HW
#define OFF_RED   (OFF_C + 128)        // 160 scratch (meanZ1 32 | cZ1 32 | lbd 2 | red)
#define SMEM_FLOATS (OFF_RED + 160)
// SMEM bytes = SMEM_FLOATS*4 = 160128

// C[i][n] = sum_k HWs[i][k] * Bs[k][n],  i<128, k<128, n<N (N=64 or 32)
// 256 threads: ty=tid>>3 (4 rows each), tx=tid&7 (N/8 cols each)
template<int N, bool RELU_ADD>
__device__ __forceinline__ void mm_hw(const float* __restrict__ HWs,
                                      const float* __restrict__ Bs,
                                      float* __restrict__ Cs,
                                      const float* __restrict__ Adds) {
    constexpr int CPT = N / 8;
    const int tid = threadIdx.x;
    const int ty = tid >> 3;
    const int tx = tid & 7;
    const int i0 = ty * 4;
    const int n0 = tx * CPT;
    float acc[4][CPT];
#pragma unroll
    for (int r = 0; r < 4; r++)
#pragma unroll
        for (int c = 0; c < CPT; c++) acc[r][c] = 0.f;

#pragma unroll 2
    for (int kb = 0; kb < 128; kb += 4) {
        float a_s[4][4];
#pragma unroll
        for (int r = 0; r < 4; r++)
            *(float4*)a_s[r] = *(const float4*)&HWs[(i0 + r) * HWS + kb];
#pragma unroll
        for (int kk = 0; kk < 4; kk++) {
            float bv[CPT];
#pragma unroll
            for (int c = 0; c < CPT; c += 4)
                *(float4*)&bv[c] = *(const float4*)&Bs[(kb + kk) * N + n0 + c];
#pragma unroll
            for (int r = 0; r < 4; r++) {
                float av = a_s[r][kk];
#pragma unroll
                for (int c = 0; c < CPT; c++)
                    acc[r][c] += av * bv[c];
            }
        }
    }
#pragma unroll
    for (int r = 0; r < 4; r++)
#pragma unroll
        for (int c = 0; c < CPT; c++) {
            float v = acc[r][c];
            if (RELU_ADD) v = fmaxf(v + Adds[(i0 + r) * N + (n0 + c)], 0.f);
            Cs[(i0 + r) * N + (n0 + c)] = v;
        }
}

__global__ __launch_bounds__(NTHREADS, 1)
void unfold_pocs_kernel(const float* __restrict__ gHW, const float* __restrict__ gx0,
                        const float* __restrict__ gnu3, const float* __restrict__ gtg,
                        const float* __restrict__ g1W0a, const float* __restrict__ g1W1a,
                        const float* __restrict__ g1W0b, const float* __restrict__ g1W1b,
                        const float* __restrict__ g2W0a, const float* __restrict__ g2W1a,
                        const float* __restrict__ g2W0b, const float* __restrict__ g2W1b,
                        float* __restrict__ out) {
    extern __shared__ float sm[];
    const int b = blockIdx.x;
    const int tid = threadIdx.x;
    float* HWs = sm + OFF_HW;
    float* xs  = sm + OFF_XS;
    float* sx1 = sm + OFF_SX1;
    float* z1  = sm + OFF_Z1;    // later: U0
    float* w64 = sm + OFF_W64;   // later: V (first 4096) / Z2 (second 4096)
    float* Tb  = sm + OFF_T;     // later: SZ2
    float* sw  = sm + OFF_SW;
    float* cC  = sm + OFF_C;
    float* red = sm + OFF_RED;

    const float* hwg = gHW + (size_t)b * (128 * 128);

    // ---- load HW (padded), x0, W64 = [g2W0a_top | g2W1a_top], small weights ----
    for (int o = tid; o < 4096; o += NTHREADS) {
        float4 v = *(const float4*)(hwg + o * 4);
        int w = o * 4;
        int row = w >> 7, col = w & 127;
        *(float4*)&HWs[row * HWS + col] = v;
    }
    for (int o = tid; o < 160; o += NTHREADS)
        *(float4*)&xs[o * 4] = *(const float4*)(gx0 + (size_t)b * 640 + o * 4);
    for (int o = tid; o < 8192; o += NTHREADS) {
        int k = o >> 6, h = o & 63;
        w64[o] = (h < 32) ? g2W0a[k * 32 + h] : g2W1a[k * 32 + (h - 32)];
    }
    for (int o = tid; o < 160; o += NTHREADS) sw[o]       = g1W0a[o];
    for (int o = tid; o < 160; o += NTHREADS) sw[160 + o] = g1W1a[o];
    for (int o = tid; o < 64;  o += NTHREADS) sw[320 + o] = g1W0b[o];
    for (int o = tid; o < 64;  o += NTHREADS) sw[384 + o] = g1W1b[o];
    for (int o = tid; o < 160; o += NTHREADS) sw[448 + o] = g2W0a[128 * 32 + o]; // W0a bottom 5x32
    for (int o = tid; o < 160; o += NTHREADS) sw[608 + o] = g2W1a[128 * 32 + o]; // W1a bottom 5x32
    for (int o = tid; o < 160; o += NTHREADS) sw[768 + o] = g2W0b[o];            // 32x5
    for (int o = tid; o < 160; o += NTHREADS) sw[928 + o] = g2W1b[o];            // 32x5
    __syncthreads();

    // ---- GNN1: SX1 = HW @ X1 (X1[k][f] = xs[f*128+k]) ; c = colmean(HW) ----
    for (int o = tid; o < 640; o += NTHREADS) {
        int i = o & 127, f = o >> 7;
        const float* hr = &HWs[i * HWS];
        const float* xv = &xs[f * 128];
        float acc = 0.f;
#pragma unroll 4
        for (int k = 0; k < 128; k += 4) {
            float4 h4 = *(const float4*)&hr[k];
            float4 x4 = *(const float4*)&xv[k];
            acc += h4.x * x4.x + h4.y * x4.y + h4.z * x4.z + h4.w * x4.w;
        }
        sx1[o] = acc;   // layout [f*128 + i]
    }
    if (tid < 128) {
        float acc = 0.f;
        for (int i = 0; i < 128; i++) acc += HWs[i * HWS + tid];
        cC[tid] = acc * (1.f / 128.f);
    }
    __syncthreads();

    // Z1 = relu(X1 @ g1W0a + SX1 @ g1W1a)   (128 x 32)
    {
        const float* w0a = sw;
        const float* w1a = sw + 160;
        for (int o = tid; o < 4096; o += NTHREADS) {
            int k = o >> 5, h = o & 31;
            float acc = 0.f;
#pragma unroll
            for (int f = 0; f < 5; f++)
                acc += xs[f * 128 + k] * w0a[f * 32 + h] + sx1[f * 128 + k] * w1a[f * 32 + h];
            z1[o] = fmaxf(acc, 0.f);
        }
    }
    __syncthreads();

    // meanZ1 and cZ1 (mean trick: mean_k(HW@Z1) = c^T Z1)
    if (tid < 32) {
        float m = 0.f, cz = 0.f;
        for (int k = 0; k < 128; k++) {
            float zv = z1[k * 32 + tid];
            m += zv;
            cz += cC[k] * zv;
        }
        red[tid] = m * (1.f / 128.f);
        red[32 + tid] = cz;
    }
    __syncthreads();
    if (tid < 2) {
        const float* w0b = sw + 320;  // 32x2
        const float* w1b = sw + 384;
        float acc = 0.f;
        for (int h = 0; h < 32; h++)
            acc += red[h] * w0b[h * 2 + tid] + red[32 + h] * w1b[h * 2 + tid];
        red[64 + tid] = fmaxf(acc, 0.f);  // lbd
    }
    __syncthreads();

    // ---- update bands s1, s4 ----
    {
        float l0 = red[64], l1 = red[65];
        if (tid < 128) {
            float s1v = xs[128 + tid];
            xs[128 + tid] = s1v - l0 * ((1.0f / 128.f) / (1.f + s1v));
            xs[512 + tid] += l1 * ((1.0f / 128.f) * 0.1f);
        }
    }
    __syncthreads();

    // ---- GNN2 restructured ----
    // T = HW @ [W0a_top | W1a_top]  (128 x 64)
    mm_hw<64, false>(HWs, w64, Tb, nullptr);
    __syncthreads();

    // U0 = T[:, :32] + X2 @ W0a_bot ; V = T[:, 32:] + X2 @ W1a_bot
    {
        const float* w0bot = sw + 448;
        const float* w1bot = sw + 608;
        float* U0 = z1;
        float* V  = w64;
        for (int o = tid; o < 4096; o += NTHREADS) {
            int k = o >> 5, h = o & 31;
            float u = Tb[k * 64 + h];
            float v = Tb[k * 64 + 32 + h];
#pragma unroll
            for (int f = 0; f < 5; f++) {
                float xv = xs[f * 128 + k];
                u += xv * w0bot[f * 32 + h];
                v += xv * w1bot[f * 32 + h];
            }
            U0[o] = u;
            V[o] = v;
        }
    }
    __syncthreads();

    // Z2 = relu(U0 + HW @ V)
    mm_hw<32, true>(HWs, w64 /*V*/, w64 + 4096 /*Z2*/, z1 /*U0*/);
    __syncthreads();

    // SZ2 = HW @ Z2
    mm_hw<32, false>(HWs, w64 + 4096, Tb /*SZ2*/, nullptr);
    __syncthreads();

    // tilde = Z2 @ W0b + SZ2 @ W1b ; x += tilde^T
    {
        const float* Z2  = w64 + 4096;
        const float* SZ2 = Tb;
        const float* w0b2 = sw + 768;  // 32x5
        const float* w1b2 = sw + 928;
        for (int o = tid; o < 640; o += NTHREADS) {
            int k = o & 127, f = o >> 7;
            float acc = 0.f;
#pragma unroll 8
            for (int h = 0; h < 32; h++)
                acc += Z2[k * 32 + h] * w0b2[h * 5 + f] + SZ2[k * 32 + h] * w1b2[h * 5 + f];
            xs[f * 128 + k] += acc;
        }
    }
    __syncthreads();

    // ---- simplex-like projection on band 0 ----
    if (tid < 128) red[tid] = xs[tid];
    __syncthreads();
    for (int s = 64; s > 0; s >>= 1) {
        if (tid < s) red[tid] += red[tid + s];
        __syncthreads();
    }
    {
        float fproj = red[0] - 10.0f;
        if (fproj > 0.f && tid < 128) xs[tid] -= fproj * (1.f / 128.f);
    }
    __syncthreads();

    // ---- band clamps (+ implicit final relu) ----
    {
        float nu3 = gnu3[0], tg = gtg[0];
        float Vnu = 1.f - 1.f / ((1.f + nu3) * (1.f + nu3));
        float Vg  = 1.f - 1.f / ((1.f + tg) * (1.f + tg));
        for (int m = tid; m < 640; m += NTHREADS) {
            float v = xs[m];
            int band = m >> 7;
            v = fmaxf(v, band == 1 ? nu3 : 0.f);
            if (band == 2) v = fminf(v, tg);
            if (band == 3) v = fminf(fmaxf(v, Vnu), Vg);
            xs[m] = v;
        }
    }
    __syncthreads();

    // ---- outputs ----
    {
        float* outx = out + (size_t)b * 640;
        for (int o = tid; o < 160; o += NTHREADS)
            *(float4*)&outx[o * 4] = *(const float4*)&xs[o * 4];
    }
    {
        const size_t BM = (size_t)Bsz * 640;
        const size_t BK = (size_t)Bsz * 128;
        if (tid < 128) {
            int k = tid;
            float p  = xs[k];
            float nu = xs[128 + k];
            float xg = xs[256 + k];
            float xv = xs[384 + k];
            float s4 = xs[512 + k];
            float f5 = 1.f - 1.f / ((1.f + xg) * (1.f + xg)) - xv;
            float f6 = sqrtf(xv) - s4;
            float dacc = 0.f;
            for (int i = 0; i < 128; i++) dacc += xs[i] * HWs[i * HWS + k];
            float top  = p * HWs[k * HWS + k];
            float down = dacc - top + 1.f;
            out[BM +            (size_t)b * 128 + k] = f5;
            out[BM +     BK +   (size_t)b * 128 + k] = f6;
            out[BM + 2 * BK +   (size_t)b * 128 + k] = top - down * xg;
            out[BM + 3 * BK +   (size_t)b * 128 + k] = nu * down - top;
        }
    }
}

extern "C" void kernel_launch(void* const* d_in, const int* in_sizes, int n_in,
                              void* d_out, int out_size) {
    const float* HW    = (const float*)d_in[2];
    const float* x0    = (const float*)d_in[3];
    const float* nu3   = (const float*)d_in[4];
    const float* tg    = (const float*)d_in[5];
    const float* g1W0a = (const float*)d_in[12];
    const float* g1W1a = (const float*)d_in[13];
    const float* g1W0b = (const float*)d_in[14];
    const float* g1W1b = (const float*)d_in[15];
    const float* g2W0a = (const float*)d_in[16];
    const float* g2W1a = (const float*)d_in[17];
    const float* g2W0b = (const float*)d_in[18];
    const float* g2W1b = (const float*)d_in[19];

    cudaFuncSetAttribute(unfold_pocs_kernel,
                         cudaFuncAttributeMaxDynamicSharedMemorySize,
                         SMEM_FLOATS * 4);

    unfold_pocs_kernel<<<Bsz, NTHREADS, SMEM_FLOATS * 4>>>(
        HW, x0, nu3, tg,
        g1W0a, g1W1a, g1W0b, g1W1b,
        g2W0a, g2W1a, g2W0b, g2W1b,
        (float*)d_out);
}

// round 2
// speedup vs baseline: 1.0959x; 1.0959x over previous
#include <cuda_runtime.h>
#include <math.h>

#define Bsz 2048
#define HWS 132          // padded HW row stride (floats), 16B aligned
#define NTHREADS 512

// ---- shared memory layout (float offsets) ----
#define OFF_HW    0                    // 128*132 = 16896
#define OFF_XS    (OFF_HW + 128*HWS)   // 640
#define OFF_SX1   (OFF_XS + 640)       // 640   (later: G, layout [f*128+k])
#define OFF_Z1    (OFF_SX1 + 640)      // 4096  (later: U0, then P0 in [0:640])
#define OFF_W64   (OFF_Z1 + 4096)      // 8192  (later: V @ +0, Z2 @ +4096)
#define OFF_T     (OFF_W64 + 8192)     // 8192  (T only)
#define OFF_SW    (OFF_T + 8192)       // 1088 small weights
#define OFF_C     (OFF_SW + 1088)      // 128 column means of HW
#define OFF_RED   (OFF_C + 128)        // 160 scratch
#define SMEM_FLOATS (OFF_RED + 160)
// SMEM bytes = SMEM_FLOATS*4 = 160128

__device__ __forceinline__ void bar_grpB() {
    asm volatile("bar.sync 1, 256;" ::: "memory");
}

__global__ __launch_bounds__(NTHREADS, 1)
void unfold_pocs_kernel(const float* __restrict__ gHW, const float* __restrict__ gx0,
                        const float* __restrict__ gnu3, const float* __restrict__ gtg,
                        const float* __restrict__ g1W0a, const float* __restrict__ g1W1a,
                        const float* __restrict__ g1W0b, const float* __restrict__ g1W1b,
                        const float* __restrict__ g2W0a, const float* __restrict__ g2W1a,
                        const float* __restrict__ g2W0b, const float* __restrict__ g2W1b,
                        float* __restrict__ out) {
    extern __shared__ float sm[];
    const int b = blockIdx.x;
    const int tid = threadIdx.x;
    float* HWs = sm + OFF_HW;
    float* xs  = sm + OFF_XS;
    float* sx1 = sm + OFF_SX1;   // later G
    float* z1  = sm + OFF_Z1;    // later U0 / P0
    float* w64 = sm + OFF_W64;   // later V(first half), Z2(second half)
    float* Tb  = sm + OFF_T;
    float* sw  = sm + OFF_SW;
    float* cC  = sm + OFF_C;
    float* red = sm + OFF_RED;

    const float* hwg = gHW + (size_t)b * (128 * 128);

    // ================= Phase 0: loads (all 512) =================
    for (int o = tid; o < 4096; o += NTHREADS) {
        float4 v = *(const float4*)(hwg + o * 4);
        int w = o * 4;
        int row = w >> 7, col = w & 127;
        *(float4*)&HWs[row * HWS + col] = v;
    }
    for (int o = tid; o < 160; o += NTHREADS)
        *(float4*)&xs[o * 4] = *(const float4*)(gx0 + (size_t)b * 640 + o * 4);
    for (int o = tid; o < 8192; o += NTHREADS) {
        int k = o >> 6, h = o & 63;
        w64[o] = (h < 32) ? g2W0a[k * 32 + h] : g2W1a[k * 32 + (h - 32)];
    }
    for (int o = tid; o < 160; o += NTHREADS) sw[o]       = g1W0a[o];
    for (int o = tid; o < 160; o += NTHREADS) sw[160 + o] = g1W1a[o];
    for (int o = tid; o < 64;  o += NTHREADS) sw[320 + o] = g1W0b[o];
    for (int o = tid; o < 64;  o += NTHREADS) sw[384 + o] = g1W1b[o];
    for (int o = tid; o < 160; o += NTHREADS) sw[448 + o] = g2W0a[128 * 32 + o]; // W0a bottom 5x32
    for (int o = tid; o < 160; o += NTHREADS) sw[608 + o] = g2W1a[128 * 32 + o]; // W1a bottom 5x32
    for (int o = tid; o < 160; o += NTHREADS) sw[768 + o] = g2W0b[o];            // 32x5
    for (int o = tid; o < 160; o += NTHREADS) sw[928 + o] = g2W1b[o];            // 32x5
    __syncthreads();

    // ================= Phase 1: split =================
    if (tid < 256) {
        // ---- Group A: T = HW @ W64 (128x64), 4x8 register tiles ----
        const int ty = tid >> 3;
        const int tx = tid & 7;
        const int i0 = ty * 4;
        const int n0 = tx * 8;
        float acc[4][8];
#pragma unroll
        for (int r = 0; r < 4; r++)
#pragma unroll
            for (int c = 0; c < 8; c++) acc[r][c] = 0.f;
#pragma unroll 2
        for (int kb = 0; kb < 128; kb += 4) {
            float a_s[4][4];
#pragma unroll
            for (int r = 0; r < 4; r++)
                *(float4*)a_s[r] = *(const float4*)&HWs[(i0 + r) * HWS + kb];
#pragma unroll
            for (int kk = 0; kk < 4; kk++) {
                float bv[8];
                *(float4*)&bv[0] = *(const float4*)&w64[(kb + kk) * 64 + n0];
                *(float4*)&bv[4] = *(const float4*)&w64[(kb + kk) * 64 + n0 + 4];
#pragma unroll
                for (int r = 0; r < 4; r++) {
                    float av = a_s[r][kk];
#pragma unroll
                    for (int c = 0; c < 8; c++) acc[r][c] += av * bv[c];
                }
            }
        }
#pragma unroll
        for (int r = 0; r < 4; r++)
#pragma unroll
            for (int c = 0; c < 8; c++)
                Tb[(i0 + r) * 64 + (n0 + c)] = acc[r][c];
    } else {
        // ---- Group B: GNN1 chain (256 threads) ----
        const int t2 = tid - 256;
        // SX1[f*128+i] = sum_k HW[i,k]*xs[f*128+k]
        for (int o = t2; o < 640; o += 256) {
            int i = o & 127, f = o >> 7;
            const float* hr = &HWs[i * HWS];
            const float* xv = &xs[f * 128];
            float acc = 0.f;
#pragma unroll 8
            for (int k = 0; k < 128; k += 4) {
                float4 h4 = *(const float4*)&hr[k];
                float4 x4 = *(const float4*)&xv[k];
                acc += h4.x * x4.x + h4.y * x4.y + h4.z * x4.z + h4.w * x4.w;
            }
            sx1[o] = acc;
        }
        if (t2 < 128) {
            float acc = 0.f;
#pragma unroll 4
            for (int i = 0; i < 128; i++) acc += HWs[i * HWS + t2];
            cC[t2] = acc * (1.f / 128.f);
        }
        bar_grpB();
        // Z1 = relu(X1@g1W0a + SX1@g1W1a) : 128x32
        {
            const float* w0a = sw;
            const float* w1a = sw + 160;
            for (int o = t2; o < 4096; o += 256) {
                int k = o >> 5, h = o & 31;
                float acc = 0.f;
#pragma unroll
                for (int f = 0; f < 5; f++)
                    acc += xs[f * 128 + k] * w0a[f * 32 + h] + sx1[f * 128 + k] * w1a[f * 32 + h];
                z1[o] = fmaxf(acc, 0.f);
            }
        }
        bar_grpB();
        if (t2 < 32) {
            float m = 0.f, cz = 0.f;
#pragma unroll 4
            for (int k = 0; k < 128; k++) {
                float zv = z1[k * 32 + t2];
                m += zv;
                cz += cC[k] * zv;
            }
            red[t2] = m * (1.f / 128.f);
            red[32 + t2] = cz;
        }
        bar_grpB();
        if (t2 < 2) {
            const float* w0b = sw + 320;
            const float* w1b = sw + 384;
            float acc = 0.f;
#pragma unroll 8
            for (int h = 0; h < 32; h++)
                acc += red[h] * w0b[h * 2 + t2] + red[32 + h] * w1b[h * 2 + t2];
            red[64 + t2] = fmaxf(acc, 0.f);  // lbd
        }
        bar_grpB();
        if (t2 < 128) {
            float l0 = red[64], l1 = red[65];
            float s1v = xs[128 + t2];
            xs[128 + t2] = s1v - l0 * ((1.0f / 128.f) / (1.f + s1v));
            xs[512 + t2] += l1 * ((1.0f / 128.f) * 0.1f);
        }
    }
    __syncthreads();

    // ================= Phase 2: U0 / V (all 512) =================
    {
        const float* w0bot = sw + 448;
        const float* w1bot = sw + 608;
        float* U0 = z1;
        float* V  = w64;   // overwrite W64 (done with it)
        for (int o = tid; o < 4096; o += NTHREADS) {
            int k = o >> 5, h = o & 31;
            float u = Tb[k * 64 + h];
            float v = Tb[k * 64 + 32 + h];
#pragma unroll
            for (int f = 0; f < 5; f++) {
                float xv = xs[f * 128 + k];
                u += xv * w0bot[f * 32 + h];
                v += xv * w1bot[f * 32 + h];
            }
            U0[o] = u;
            V[o] = v;
        }
    }
    __syncthreads();

    // ================= Phase 3: Z2 = relu(U0 + HW@V) (all 512) =================
    {
        const float* V  = w64;
        const float* U0 = z1;
        float* Z2 = w64 + 4096;
        const int ty = tid >> 3;     // 0..63 -> 2 rows
        const int tx = tid & 7;      // 0..7  -> 4 cols
        const int i0 = ty * 2;
        const int n0 = tx * 4;
        float acc[2][4];
#pragma unroll
        for (int r = 0; r < 2; r++)
#pragma unroll
            for (int c = 0; c < 4; c++) acc[r][c] = 0.f;
#pragma unroll 2
        for (int kb = 0; kb < 128; kb += 4) {
            float a_s[2][4];
#pragma unroll
            for (int r = 0; r < 2; r++)
                *(float4*)a_s[r] = *(const float4*)&HWs[(i0 + r) * HWS + kb];
#pragma unroll
            for (int kk = 0; kk < 4; kk++) {
                float4 bv = *(const float4*)&V[(kb + kk) * 32 + n0];
#pragma unroll
                for (int r = 0; r < 2; r++) {
                    float av = a_s[r][kk];
                    acc[r][0] += av * bv.x;
                    acc[r][1] += av * bv.y;
                    acc[r][2] += av * bv.z;
                    acc[r][3] += av * bv.w;
                }
            }
        }
#pragma unroll
        for (int r = 0; r < 2; r++)
#pragma unroll
            for (int c = 0; c < 4; c++) {
                float v = acc[r][c] + U0[(i0 + r) * 32 + (n0 + c)];
                Z2[(i0 + r) * 32 + (n0 + c)] = fmaxf(v, 0.f);
            }
    }
    __syncthreads();

    // ================= Phase 4: G = Z2@W1b, P0 = Z2@W0b (all 512) =================
    {
        const float* Z2 = w64 + 4096;
        const float* w0b2 = sw + 768;  // 32x5
        const float* w1b2 = sw + 928;  // 32x5
        for (int o = tid; o < 1280; o += NTHREADS) {
            if (o < 640) {
                int k = o & 127, f = o >> 7;
                float acc = 0.f;
#pragma unroll 8
                for (int h = 0; h < 32; h++) acc += Z2[k * 32 + h] * w1b2[h * 5 + f];
                sx1[f * 128 + k] = acc;          // G, [f*128+k]
            } else {
                int o2 = o - 640;
                int k = o2 & 127, f = o2 >> 7;
                float acc = 0.f;
#pragma unroll 8
                for (int h = 0; h < 32; h++) acc += Z2[k * 32 + h] * w0b2[h * 5 + f];
                z1[o2] = acc;                    // P0, [f*128+k]
            }
        }
    }
    __syncthreads();

    // ================= Phase 5: x += P0 + HW@G (all 512, 640 outputs) =================
    for (int o = tid; o < 640; o += NTHREADS) {
        int k = o & 127, f = o >> 7;
        const float* hr = &HWs[k * HWS];
        const float* gv = &sx1[f * 128];
        float acc = 0.f;
#pragma unroll 8
        for (int j = 0; j < 128; j += 4) {
            float4 h4 = *(const float4*)&hr[j];
            float4 g4 = *(const float4*)&gv[j];
            acc += h4.x * g4.x + h4.y * g4.y + h4.z * g4.z + h4.w * g4.w;
        }
        xs[o] += z1[o] + acc;
    }
    __syncthreads();

    // ================= projection on band 0 =================
    if (tid < 32) {
        float s = xs[tid] + xs[tid + 32] + xs[tid + 64] + xs[tid + 96];
#pragma unroll
        for (int m = 16; m > 0; m >>= 1) s += __shfl_xor_sync(0xffffffffu, s, m);
        if (tid == 0) red[0] = s;
    }
    __syncthreads();
    {
        float fproj = red[0] - 10.0f;
        if (fproj > 0.f && tid < 128) xs[tid] -= fproj * (1.f / 128.f);
    }
    __syncthreads();

    // ================= band clamps =================
    {
        float nu3 = gnu3[0], tg = gtg[0];
        float Vnu = 1.f - 1.f / ((1.f + nu3) * (1.f + nu3));
        float Vg  = 1.f - 1.f / ((1.f + tg) * (1.f + tg));
        for (int m = tid; m < 640; m += NTHREADS) {
            float v = xs[m];
            int band = m >> 7;
            v = fmaxf(v, band == 1 ? nu3 : 0.f);
            if (band == 2) v = fminf(v, tg);
            if (band == 3) v = fminf(fmaxf(v, Vnu), Vg);
            xs[m] = v;
        }
    }
    __syncthreads();

    // ================= outputs =================
    {
        float* outx = out + (size_t)b * 640;
        for (int o = tid; o < 160; o += NTHREADS)
            *(float4*)&outx[o * 4] = *(const float4*)&xs[o * 4];
    }
    {
        const size_t BM = (size_t)Bsz * 640;
        const size_t BK = (size_t)Bsz * 128;
        if (tid < 128) {
            int k = tid;
            float p  = xs[k];
            float nu = xs[128 + k];
            float xg = xs[256 + k];
            float xv = xs[384 + k];
            float s4 = xs[512 + k];
            float f5 = 1.f - 1.f / ((1.f + xg) * (1.f + xg)) - xv;
            float f6 = sqrtf(xv) - s4;
            float dacc = 0.f;
#pragma unroll 4
            for (int i = 0; i < 128; i++) dacc += xs[i] * HWs[i * HWS + k];
            float top  = p * HWs[k * HWS + k];
            float down = dacc - top + 1.f;
            out[BM +            (size_t)b * 128 + k] = f5;
            out[BM +     BK +   (size_t)b * 128 + k] = f6;
            out[BM + 2 * BK +   (size_t)b * 128 + k] = top - down * xg;
            out[BM + 3 * BK +   (size_t)b * 128 + k] = nu * down - top;
        }
    }
}

extern "C" void kernel_launch(void* const* d_in, const int* in_sizes, int n_in,
                              void* d_out, int out_size) {
    const float* HW    = (const float*)d_in[2];
    const float* x0    = (const float*)d_in[3];
    const float* nu3   = (const float*)d_in[4];
    const float* tg    = (const float*)d_in[5];
    const float* g1W0a = (const float*)d_in[12];
    const float* g1W1a = (const float*)d_in[13];
    const float* g1W0b = (const float*)d_in[14];
    const float* g1W1b = (const float*)d_in[15];
    const float* g2W0a = (const float*)d_in[16];
    const float* g2W1a = (const float*)d_in[17];
    const float* g2W0b = (const float*)d_in[18];
    const float* g2W1b = (const float*)d_in[19];

    cudaFuncSetAttribute(unfold_pocs_kernel,
                         cudaFuncAttributeMaxDynamicSharedMemorySize,
                         SMEM_FLOATS * 4);

    unfold_pocs_kernel<<<Bsz, NTHREADS, SMEM_FLOATS * 4>>>(
        HW, x0, nu3, tg,
        g1W0a, g1W1a, g1W0b, g1W1b,
        g2W0a, g2W1a, g2W0b, g2W1b,
        (float*)d_out);
}

// round 3
// speedup vs baseline: 1.3269x; 1.2108x over previous
#include <cuda_runtime.h>
#include <math.h>

#define Bsz 2048
#define HWS 132          // padded HW row stride (floats); 33 float4s (odd) -> conflict-free columns
#define NTHREADS 512

// ---- shared memory layout (float offsets) ----
#define OFF_HW    0                     // 128*132 = 16896
#define OFF_XS    (OFF_HW + 128*HWS)    // 640
#define OFF_SX1   (OFF_XS + 640)        // 640   (later: G [f*128+k])
#define OFF_Z1    (OFF_SX1 + 640)       // 4096  (SX1 partials, Z1, U0, P0)
#define OFF_W64   (OFF_Z1 + 4096)       // 8192  (weights; later V in first half)
#define OFF_T     (OFF_W64 + 8192)      // 8192  (T; P3 partial; P5 partials; dacc partials)
#define OFF_Z2T   (OFF_T + 8192)        // 32*132 = 4224 (Z2 transposed)
#define OFF_SW    (OFF_Z2T + 4224)      // 1088 small weights
#define OFF_C     (OFF_SW + 1088)       // 128 column means of HW
#define OFF_RED   (OFF_C + 128)         // 160 scratch
#define SMEM_FLOATS (OFF_RED + 160)     // 44256 floats = 177024 B

__device__ __forceinline__ void bar_grpB() {
    asm volatile("bar.sync 1, 256;" ::: "memory");
}

__global__ __launch_bounds__(NTHREADS, 1)
void unfold_pocs_kernel(const float* __restrict__ gHW, const float* __restrict__ gx0,
                        const float* __restrict__ gnu3, const float* __restrict__ gtg,
                        const float* __restrict__ g1W0a, const float* __restrict__ g1W1a,
                        const float* __restrict__ g1W0b, const float* __restrict__ g1W1b,
                        const float* __restrict__ g2W0a, const float* __restrict__ g2W1a,
                        const float* __restrict__ g2W0b, const float* __restrict__ g2W1b,
                        float* __restrict__ out) {
    extern __shared__ float sm[];
    const int b = blockIdx.x;
    const int tid = threadIdx.x;
    float* HWs = sm + OFF_HW;
    float* xs  = sm + OFF_XS;
    float* sx1 = sm + OFF_SX1;   // later G
    float* z1  = sm + OFF_Z1;    // SX1 partials -> Z1 -> U0 -> P0
    float* w64 = sm + OFF_W64;   // weights -> V (first 4096)
    float* Tb  = sm + OFF_T;
    float* z2t = sm + OFF_Z2T;
    float* sw  = sm + OFF_SW;
    float* cC  = sm + OFF_C;
    float* red = sm + OFF_RED;

    const float* hwg = gHW + (size_t)b * (128 * 128);

    // ================= Phase 0: loads =================
    for (int o = tid; o < 4096; o += NTHREADS) {
        float4 v = *(const float4*)(hwg + o * 4);
        int w = o * 4;
        int row = w >> 7, col = w & 127;
        *(float4*)&HWs[row * HWS + col] = v;
    }
    for (int o = tid; o < 160; o += NTHREADS)
        *(float4*)&xs[o * 4] = *(const float4*)(gx0 + (size_t)b * 640 + o * 4);
    for (int o = tid; o < 8192; o += NTHREADS) {
        int k = o >> 6, h = o & 63;
        w64[o] = (h < 32) ? g2W0a[k * 32 + h] : g2W1a[k * 32 + (h - 32)];
    }
    for (int o = tid; o < 160; o += NTHREADS) sw[o]       = g1W0a[o];
    for (int o = tid; o < 160; o += NTHREADS) sw[160 + o] = g1W1a[o];
    for (int o = tid; o < 64;  o += NTHREADS) sw[320 + o] = g1W0b[o];
    for (int o = tid; o < 64;  o += NTHREADS) sw[384 + o] = g1W1b[o];
    for (int o = tid; o < 160; o += NTHREADS) sw[448 + o] = g2W0a[128 * 32 + o]; // W0a bottom 5x32
    for (int o = tid; o < 160; o += NTHREADS) sw[608 + o] = g2W1a[128 * 32 + o]; // W1a bottom 5x32
    for (int o = tid; o < 160; o += NTHREADS) sw[768 + o] = g2W0b[o];            // 32x5
    for (int o = tid; o < 160; o += NTHREADS) sw[928 + o] = g2W1b[o];            // 32x5
    __syncthreads();

    // ================= Phase 1: split =================
    if (tid < 256) {
        // ---- Group A: T = HW @ W64 (128x64), 4x8 register tiles ----
        const int ty = tid >> 3;
        const int tx = tid & 7;
        const int i0 = ty * 4;
        const int n0 = tx * 8;
        float acc[4][8];
#pragma unroll
        for (int r = 0; r < 4; r++)
#pragma unroll
            for (int c = 0; c < 8; c++) acc[r][c] = 0.f;
#pragma unroll 2
        for (int kb = 0; kb < 128; kb += 4) {
            float a_s[4][4];
#pragma unroll
            for (int r = 0; r < 4; r++)
                *(float4*)a_s[r] = *(const float4*)&HWs[(i0 + r) * HWS + kb];
#pragma unroll
            for (int kk = 0; kk < 4; kk++) {
                float bv[8];
                *(float4*)&bv[0] = *(const float4*)&w64[(kb + kk) * 64 + n0];
                *(float4*)&bv[4] = *(const float4*)&w64[(kb + kk) * 64 + n0 + 4];
#pragma unroll
                for (int r = 0; r < 4; r++) {
                    float av = a_s[r][kk];
#pragma unroll
                    for (int c = 0; c < 8; c++) acc[r][c] += av * bv[c];
                }
            }
        }
#pragma unroll
        for (int r = 0; r < 4; r++)
#pragma unroll
            for (int c = 0; c < 8; c++)
                Tb[(i0 + r) * 64 + (n0 + c)] = acc[r][c];
    } else {
        // ---- Group B: GNN1 chain (256 threads) ----
        const int t2 = tid - 256;
        // SX1 partials: thread (i, h2): sum over j in [64*h2, 64*h2+64)
        {
            const int i = t2 & 127, h2 = t2 >> 7;
            const int jb = 64 * h2;
            const float* hr = &HWs[i * HWS + jb];
            float a0 = 0.f, a1 = 0.f, a2 = 0.f, a3 = 0.f, a4 = 0.f;
#pragma unroll 4
            for (int j = 0; j < 64; j += 4) {
                float4 h4 = *(const float4*)&hr[j];
                float4 x0 = *(const float4*)&xs[0 * 128 + jb + j];
                float4 x1 = *(const float4*)&xs[1 * 128 + jb + j];
                float4 x2 = *(const float4*)&xs[2 * 128 + jb + j];
                float4 x3 = *(const float4*)&xs[3 * 128 + jb + j];
                float4 x4 = *(const float4*)&xs[4 * 128 + jb + j];
                a0 += h4.x * x0.x + h4.y * x0.y + h4.z * x0.z + h4.w * x0.w;
                a1 += h4.x * x1.x + h4.y * x1.y + h4.z * x1.z + h4.w * x1.w;
                a2 += h4.x * x2.x + h4.y * x2.y + h4.z * x2.z + h4.w * x2.w;
                a3 += h4.x * x3.x + h4.y * x3.y + h4.z * x3.z + h4.w * x3.w;
                a4 += h4.x * x4.x + h4.y * x4.y + h4.z * x4.z + h4.w * x4.w;
            }
            z1[h2 * 640 + 0 * 128 + i] = a0;
            z1[h2 * 640 + 1 * 128 + i] = a1;
            z1[h2 * 640 + 2 * 128 + i] = a2;
            z1[h2 * 640 + 3 * 128 + i] = a3;
            z1[h2 * 640 + 4 * 128 + i] = a4;
        }
        if (t2 < 128) {
            float acc = 0.f;
#pragma unroll 4
            for (int i = 0; i < 128; i++) acc += HWs[i * HWS + t2];
            cC[t2] = acc * (1.f / 128.f);
        }
        bar_grpB();
        for (int o = t2; o < 640; o += 256) sx1[o] = z1[o] + z1[640 + o];
        bar_grpB();
        // Z1 = relu(X1@g1W0a + SX1@g1W1a) : 128x32
        {
            const float* w0a = sw;
            const float* w1a = sw + 160;
            for (int o = t2; o < 4096; o += 256) {
                int k = o >> 5, h = o & 31;
                float acc = 0.f;
#pragma unroll
                for (int f = 0; f < 5; f++)
                    acc += xs[f * 128 + k] * w0a[f * 32 + h] + sx1[f * 128 + k] * w1a[f * 32 + h];
                z1[o] = fmaxf(acc, 0.f);
            }
        }
        bar_grpB();
        if (t2 < 32) {
            float m = 0.f, cz = 0.f;
#pragma unroll 4
            for (int k = 0; k < 128; k++) {
                float zv = z1[k * 32 + t2];
                m += zv;
                cz += cC[k] * zv;
            }
            red[t2] = m * (1.f / 128.f);
            red[32 + t2] = cz;
        }
        bar_grpB();
        if (t2 < 2) {
            const float* w0b = sw + 320;
            const float* w1b = sw + 384;
            float acc = 0.f;
#pragma unroll 8
            for (int h = 0; h < 32; h++)
                acc += red[h] * w0b[h * 2 + t2] + red[32 + h] * w1b[h * 2 + t2];
            red[64 + t2] = fmaxf(acc, 0.f);  // lbd
        }
        bar_grpB();
        if (t2 < 128) {
            float l0 = red[64], l1 = red[65];
            float s1v = xs[128 + t2];
            xs[128 + t2] = s1v - l0 * ((1.0f / 128.f) / (1.f + s1v));
            xs[512 + t2] += l1 * ((1.0f / 128.f) * 0.1f);
        }
    }
    __syncthreads();

    // ================= Phase 2: U0 / V =================
    {
        const float* w0bot = sw + 448;
        const float* w1bot = sw + 608;
        float* U0 = z1;
        float* V  = w64;
        for (int o = tid; o < 4096; o += NTHREADS) {
            int k = o >> 5, h = o & 31;
            float u = Tb[k * 64 + h];
            float v = Tb[k * 64 + 32 + h];
#pragma unroll
            for (int f = 0; f < 5; f++) {
                float xv = xs[f * 128 + k];
                u += xv * w0bot[f * 32 + h];
                v += xv * w1bot[f * 32 + h];
            }
            U0[o] = u;
            V[o] = v;
        }
    }
    __syncthreads();

    // ================= Phase 3: Z2T = relu(U0 + HW@V)^T, K-split =================
    {
        const float* V  = w64;
        const float* U0 = z1;
        const int g  = tid >> 8;       // K half
        const int t  = tid & 255;
        const int ty = t >> 3;
        const int tx = t & 7;
        const int i0 = ty * 4;
        const int n0 = tx * 4;
        const int kbase = g * 64;
        float acc[4][4];
#pragma unroll
        for (int r = 0; r < 4; r++)
#pragma unroll
            for (int c = 0; c < 4; c++) acc[r][c] = 0.f;
#pragma unroll 2
        for (int kb = kbase; kb < kbase + 64; kb += 4) {
            float a_s[4][4];
#pragma unroll
            for (int r = 0; r < 4; r++)
                *(float4*)a_s[r] = *(const float4*)&HWs[(i0 + r) * HWS + kb];
#pragma unroll
            for (int kk = 0; kk < 4; kk++) {
                float4 bv = *(const float4*)&V[(kb + kk) * 32 + n0];
#pragma unroll
                for (int r = 0; r < 4; r++) {
                    float av = a_s[r][kk];
                    acc[r][0] += av * bv.x;
                    acc[r][1] += av * bv.y;
                    acc[r][2] += av * bv.z;
                    acc[r][3] += av * bv.w;
                }
            }
        }
        if (g == 1) {
#pragma unroll
            for (int r = 0; r < 4; r++)
#pragma unroll
                for (int c = 0; c < 4; c++)
                    Tb[(i0 + r) * 32 + (n0 + c)] = acc[r][c];
        }
        __syncthreads();
        if (g == 0) {
#pragma unroll
            for (int r = 0; r < 4; r++)
#pragma unroll
                for (int c = 0; c < 4; c++) {
                    int idx = (i0 + r) * 32 + (n0 + c);
                    float v = acc[r][c] + Tb[idx] + U0[idx];
                    z2t[(n0 + c) * HWS + (i0 + r)] = fmaxf(v, 0.f);
                }
        }
    }
    __syncthreads();

    // ================= Phase 4: G = Z2@W1b (->sx1), P0 = Z2@W0b (->z1) =================
    {
        const float* w0b2 = sw + 768;  // 32x5
        const float* w1b2 = sw + 928;  // 32x5
        for (int o = tid; o < 1280; o += NTHREADS) {
            int o2 = (o < 640) ? o : (o - 640);
            int k = o2 & 127, f = o2 >> 7;
            const float* wv = (o < 640) ? w1b2 : w0b2;
            float acc = 0.f;
#pragma unroll 8
            for (int h = 0; h < 32; h++)
                acc += z2t[h * HWS + k] * wv[h * 5 + f];
            if (o < 640) sx1[f * 128 + k] = acc;   // G
            else         z1[o2] = acc;             // P0 [f*128+k]
        }
    }
    __syncthreads();

    // ================= Phase 5: partials of HW@G (j-split 4-way) =================
    {
        const int k = tid & 127, q = tid >> 7;
        const int jb = 32 * q;
        const float* hr = &HWs[k * HWS + jb];
        float a0 = 0.f, a1 = 0.f, a2 = 0.f, a3 = 0.f, a4 = 0.f;
#pragma unroll 4
        for (int j = 0; j < 32; j += 4) {
            float4 h4 = *(const float4*)&hr[j];
            float4 g0 = *(const float4*)&sx1[0 * 128 + jb + j];
            float4 g1 = *(const float4*)&sx1[1 * 128 + jb + j];
            float4 g2 = *(const float4*)&sx1[2 * 128 + jb + j];
            float4 g3 = *(const float4*)&sx1[3 * 128 + jb + j];
            float4 g4 = *(const float4*)&sx1[4 * 128 + jb + j];
            a0 += h4.x * g0.x + h4.y * g0.y + h4.z * g0.z + h4.w * g0.w;
            a1 += h4.x * g1.x + h4.y * g1.y + h4.z * g1.z + h4.w * g1.w;
            a2 += h4.x * g2.x + h4.y * g2.y + h4.z * g2.z + h4.w * g2.w;
            a3 += h4.x * g3.x + h4.y * g3.y + h4.z * g3.z + h4.w * g3.w;
            a4 += h4.x * g4.x + h4.y * g4.y + h4.z * g4.z + h4.w * g4.w;
        }
        Tb[q * 640 + 0 * 128 + k] = a0;
        Tb[q * 640 + 1 * 128 + k] = a1;
        Tb[q * 640 + 2 * 128 + k] = a2;
        Tb[q * 640 + 3 * 128 + k] = a3;
        Tb[q * 640 + 4 * 128 + k] = a4;
    }
    __syncthreads();
    // x += P0 + HW@G
    for (int o = tid; o < 640; o += NTHREADS)
        xs[o] += z1[o] + Tb[o] + Tb[640 + o] + Tb[1280 + o] + Tb[1920 + o];
    __syncthreads();

    // ================= band-0 sum =================
    if (tid < 32) {
        float s = xs[tid] + xs[tid + 32] + xs[tid + 64] + xs[tid + 96];
#pragma unroll
        for (int m = 16; m > 0; m >>= 1) s += __shfl_xor_sync(0xffffffffu, s, m);
        if (tid == 0) red[0] = s;
    }
    __syncthreads();

    // ================= projection + band clamps (fused) =================
    {
        float fproj = red[0] - 10.0f;
        float nu3 = gnu3[0], tg = gtg[0];
        float Vnu = 1.f - 1.f / ((1.f + nu3) * (1.f + nu3));
        float Vg  = 1.f - 1.f / ((1.f + tg) * (1.f + tg));
        for (int m = tid; m < 640; m += NTHREADS) {
            float v = xs[m];
            int band = m >> 7;
            if (band == 0 && fproj > 0.f) v -= fproj * (1.f / 128.f);
            v = fmaxf(v, band == 1 ? nu3 : 0.f);
            if (band == 2) v = fminf(v, tg);
            if (band == 3) v = fminf(fmaxf(v, Vnu), Vg);
            xs[m] = v;
        }
    }
    __syncthreads();

    // ================= outputs: x write + dacc partials =================
    {
        float* outx = out + (size_t)b * 640;
        for (int o = tid; o < 160; o += NTHREADS)
            *(float4*)&outx[o * 4] = *(const float4*)&xs[o * 4];
        const int k = tid & 127, q = tid >> 7;
        float acc = 0.f;
#pragma unroll 8
        for (int i = 32 * q; i < 32 * q + 32; i++)
            acc += xs[i] * HWs[i * HWS + k];
        Tb[q * 128 + k] = acc;
    }
    __syncthreads();
    {
        const size_t BM = (size_t)Bsz * 640;
        const size_t BK = (size_t)Bsz * 128;
        if (tid < 128) {
            int k = tid;
            float p  = xs[k];
            float nu = xs[128 + k];
            float xg = xs[256 + k];
            float xv = xs[384 + k];
            float s4 = xs[512 + k];
            float f5 = 1.f - 1.f / ((1.f + xg) * (1.f + xg)) - xv;
            float f6 = sqrtf(xv) - s4;
            float dacc = Tb[k] + Tb[128 + k] + Tb[256 + k] + Tb[384 + k];
            float top  = p * HWs[k * HWS + k];
            float down = dacc - top + 1.f;
            out[BM +            (size_t)b * 128 + k] = f5;
            out[BM +     BK +   (size_t)b * 128 + k] = f6;
            out[BM + 2 * BK +   (size_t)b * 128 + k] = top - down * xg;
            out[BM + 3 * BK +   (size_t)b * 128 + k] = nu * down - top;
        }
    }
}

extern "C" void kernel_launch(void* const* d_in, const int* in_sizes, int n_in,
                              void* d_out, int out_size) {
    const float* HW    = (const float*)d_in[2];
    const float* x0    = (const float*)d_in[3];
    const float* nu3   = (const float*)d_in[4];
    const float* tg    = (const float*)d_in[5];
    const float* g1W0a = (const float*)d_in[12];
    const float* g1W1a = (const float*)d_in[13];
    const float* g1W0b = (const float*)d_in[14];
    const float* g1W1b = (const float*)d_in[15];
    const float* g2W0a = (const float*)d_in[16];
    const float* g2W1a = (const float*)d_in[17];
    const float* g2W0b = (const float*)d_in[18];
    const float* g2W1b = (const float*)d_in[19];

    cudaFuncSetAttribute(unfold_pocs_kernel,
                         cudaFuncAttributeMaxDynamicSharedMemorySize,
                         SMEM_FLOATS * 4);

    unfold_pocs_kernel<<<Bsz, NTHREADS, SMEM_FLOATS * 4>>>(
        HW, x0, nu3, tg,
        g1W0a, g1W1a, g1W0b, g1W1b,
        g2W0a, g2W1a, g2W0b, g2W1b,
        (float*)d_out);
}

// round 4
// speedup vs baseline: 1.6566x; 1.2484x over previous
#include <cuda_runtime.h>
#include <math.h>

#define Bsz 2048
#define HWS 132
#define NTHREADS 512

typedef unsigned long long ull;

// ---- shared memory layout (float offsets) ----
#define OFF_HW   0                      // 16896
#define OFF_XS   16896                  // 640
#define OFF_SX1  17536                  // 640 (later G)
#define OFF_U0   18176                  // 4352: SX1 partials -> Z1 -> U0(stride 34) -> P0
#define OFF_W64  22528                  // 8192: W64 -> V(stride 32, first 4096)
#define OFF_T    30720                  // 17408: T(8192) -> phase3 partials(4*4352) -> phase5/dacc partials
#define OFF_Z2T  48128                  // 4224 (32 x 132)
#define OFF_SW   52352                  // 1088
#define OFF_C    53440                  // 128
#define OFF_RED  53568                  // 160
#define SMEM_FLOATS 53728               // 214912 bytes

__device__ __forceinline__ ull dup2(float x) {
    ull r; asm("mov.b64 %0, {%1, %1};" : "=l"(r) : "f"(x)); return r;
}
#define FMA2(acc, a, b) asm("fma.rn.f32x2 %0, %1, %2, %0;" : "+l"(acc) : "l"(a), "l"(b))
__device__ __forceinline__ float hadd2(ull v) {
    float lo, hi; asm("mov.b64 {%0, %1}, %2;" : "=f"(lo), "=f"(hi) : "l"(v)); return lo + hi;
}

__device__ __forceinline__ void bar_grpB() {
    asm volatile("bar.sync 1, 256;" ::: "memory");
}

__global__ __launch_bounds__(NTHREADS, 1)
void unfold_pocs_kernel(const float* __restrict__ gHW, const float* __restrict__ gx0,
                        const float* __restrict__ gnu3, const float* __restrict__ gtg,
                        const float* __restrict__ g1W0a, const float* __restrict__ g1W1a,
                        const float* __restrict__ g1W0b, const float* __restrict__ g1W1b,
                        const float* __restrict__ g2W0a, const float* __restrict__ g2W1a,
                        const float* __restrict__ g2W0b, const float* __restrict__ g2W1b,
                        float* __restrict__ out) {
    extern __shared__ float sm[];
    const int b = blockIdx.x;
    const int tid = threadIdx.x;
    float* HWs = sm + OFF_HW;
    float* xs  = sm + OFF_XS;
    float* sx1 = sm + OFF_SX1;
    float* u0r = sm + OFF_U0;    // SX1 partials / Z1 / U0 / P0
    float* w64 = sm + OFF_W64;   // weights -> V
    float* Tb  = sm + OFF_T;
    float* z2t = sm + OFF_Z2T;
    float* sw  = sm + OFF_SW;
    float* cC  = sm + OFF_C;
    float* red = sm + OFF_RED;

    const float* hwg = gHW + (size_t)b * (128 * 128);

    // ================= Phase 0: loads =================
    for (int o = tid; o < 4096; o += NTHREADS) {
        float4 v = *(const float4*)(hwg + o * 4);
        int w = o * 4;
        int row = w >> 7, col = w & 127;
        *(float4*)&HWs[row * HWS + col] = v;
    }
    for (int o = tid; o < 160; o += NTHREADS)
        *(float4*)&xs[o * 4] = *(const float4*)(gx0 + (size_t)b * 640 + o * 4);
    for (int o = tid; o < 8192; o += NTHREADS) {
        int k = o >> 6, h = o & 63;
        w64[o] = (h < 32) ? g2W0a[k * 32 + h] : g2W1a[k * 32 + (h - 32)];
    }
    for (int o = tid; o < 160; o += NTHREADS) sw[o]       = g1W0a[o];
    for (int o = tid; o < 160; o += NTHREADS) sw[160 + o] = g1W1a[o];
    for (int o = tid; o < 64;  o += NTHREADS) sw[320 + o] = g1W0b[o];
    for (int o = tid; o < 64;  o += NTHREADS) sw[384 + o] = g1W1b[o];
    for (int o = tid; o < 160; o += NTHREADS) sw[448 + o] = g2W0a[128 * 32 + o];
    for (int o = tid; o < 160; o += NTHREADS) sw[608 + o] = g2W1a[128 * 32 + o];
    for (int o = tid; o < 160; o += NTHREADS) sw[768 + o] = g2W0b[o];
    for (int o = tid; o < 160; o += NTHREADS) sw[928 + o] = g2W1b[o];
    __syncthreads();

    // ================= Phase 1: split =================
    if (tid < 256) {
        // ---- Group A: T = HW @ W64 (128x64), 8x4 tiles, c-paired f32x2 ----
        const int ty = tid >> 4;      // 0..15 ; rows = ty + 16r
        const int tx = tid & 15;      // 0..15 ; cols n0 = 4*tx
        const int n0 = tx * 4;
        ull acc[8][2];
#pragma unroll
        for (int r = 0; r < 8; r++) { acc[r][0] = 0ull; acc[r][1] = 0ull; }
#pragma unroll 4
        for (int kb = 0; kb < 128; kb += 4) {
            float4 av[8];
#pragma unroll
            for (int r = 0; r < 8; r++)
                av[r] = *(const float4*)&HWs[(ty + 16 * r) * HWS + kb];
#pragma unroll
            for (int kk = 0; kk < 4; kk++) {
                ulonglong2 bv = *(const ulonglong2*)&w64[(kb + kk) * 64 + n0];
#pragma unroll
                for (int r = 0; r < 8; r++) {
                    float a = (kk == 0) ? av[r].x : (kk == 1) ? av[r].y : (kk == 2) ? av[r].z : av[r].w;
                    ull pa = dup2(a);
                    FMA2(acc[r][0], pa, bv.x);
                    FMA2(acc[r][1], pa, bv.y);
                }
            }
        }
#pragma unroll
        for (int r = 0; r < 8; r++) {
            *(ull*)&Tb[(ty + 16 * r) * 64 + n0]     = acc[r][0];
            *(ull*)&Tb[(ty + 16 * r) * 64 + n0 + 2] = acc[r][1];
        }
    } else {
        // ---- Group B: GNN1 chain (256 threads) ----
        const int t2 = tid - 256;
        // SX1 partials, k-paired f32x2
        {
            const int i = t2 & 127, h2 = t2 >> 7;
            const int jb = 64 * h2;
            const float* hr = &HWs[i * HWS + jb];
            ull a2[5] = {0ull, 0ull, 0ull, 0ull, 0ull};
#pragma unroll 4
            for (int j = 0; j < 64; j += 4) {
                ulonglong2 h2v = *(const ulonglong2*)&hr[j];
#pragma unroll
                for (int f = 0; f < 5; f++) {
                    ulonglong2 xv = *(const ulonglong2*)&xs[f * 128 + jb + j];
                    FMA2(a2[f], h2v.x, xv.x);
                    FMA2(a2[f], h2v.y, xv.y);
                }
            }
#pragma unroll
            for (int f = 0; f < 5; f++)
                u0r[h2 * 640 + f * 128 + i] = hadd2(a2[f]);
        }
        if (t2 < 128) {
            float acc = 0.f;
#pragma unroll 4
            for (int i = 0; i < 128; i++) acc += HWs[i * HWS + t2];
            cC[t2] = acc * (1.f / 128.f);
        }
        bar_grpB();
        for (int o = t2; o < 640; o += 256) sx1[o] = u0r[o] + u0r[640 + o];
        bar_grpB();
        // Z1 = relu(X1@g1W0a + SX1@g1W1a) : 128x32  (into u0r)
        {
            const float* w0a = sw;
            const float* w1a = sw + 160;
            for (int o = t2; o < 4096; o += 256) {
                int k = o >> 5, h = o & 31;
                float acc = 0.f;
#pragma unroll
                for (int f = 0; f < 5; f++)
                    acc += xs[f * 128 + k] * w0a[f * 32 + h] + sx1[f * 128 + k] * w1a[f * 32 + h];
                u0r[o] = fmaxf(acc, 0.f);
            }
        }
        bar_grpB();
        if (t2 < 32) {
            float m = 0.f, cz = 0.f;
#pragma unroll 4
            for (int k = 0; k < 128; k++) {
                float zv = u0r[k * 32 + t2];
                m += zv;
                cz += cC[k] * zv;
            }
            red[t2] = m * (1.f / 128.f);
            red[32 + t2] = cz;
        }
        bar_grpB();
        if (t2 < 2) {
            const float* w0b = sw + 320;
            const float* w1b = sw + 384;
            float acc = 0.f;
#pragma unroll 8
            for (int h = 0; h < 32; h++)
                acc += red[h] * w0b[h * 2 + t2] + red[32 + h] * w1b[h * 2 + t2];
            red[64 + t2] = fmaxf(acc, 0.f);
        }
        bar_grpB();
        if (t2 < 128) {
            float l0 = red[64], l1 = red[65];
            float s1v = xs[128 + t2];
            xs[128 + t2] = s1v - l0 * ((1.0f / 128.f) / (1.f + s1v));
            xs[512 + t2] += l1 * ((1.0f / 128.f) * 0.1f);
        }
    }
    __syncthreads();

    // ================= Phase 2: U0(stride 34) / V(stride 32) =================
    {
        const float* w0bot = sw + 448;
        const float* w1bot = sw + 608;
        float* V = w64;
        for (int o = tid; o < 4096; o += NTHREADS) {
            int k = o >> 5, h = o & 31;
            float u = Tb[k * 64 + h];
            float v = Tb[k * 64 + 32 + h];
#pragma unroll
            for (int f = 0; f < 5; f++) {
                float xv = xs[f * 128 + k];
                u += xv * w0bot[f * 32 + h];
                v += xv * w1bot[f * 32 + h];
            }
            u0r[k * 34 + h] = u;
            V[k * 32 + h] = v;
        }
    }
    __syncthreads();

    // ================= Phase 3: partials of HW@V, 8x4 tiles c-paired, K-split 4 =================
    {
        const float* V = w64;
        const int g  = tid >> 7;        // 0..3 K quarter
        const int tt = tid & 127;
        const int ty = tt >> 3;         // 0..15 ; rows = ty + 16r
        const int tx = tt & 7;          // 0..7  ; cols n0 = 4*tx
        const int n0 = tx * 4;
        const int kbase = g * 32;
        ull acc[8][2];
#pragma unroll
        for (int r = 0; r < 8; r++) { acc[r][0] = 0ull; acc[r][1] = 0ull; }
#pragma unroll
        for (int kb = kbase; kb < kbase + 32; kb += 4) {
            float4 av[8];
#pragma unroll
            for (int r = 0; r < 8; r++)
                av[r] = *(const float4*)&HWs[(ty + 16 * r) * HWS + kb];
#pragma unroll
            for (int kk = 0; kk < 4; kk++) {
                ulonglong2 bv = *(const ulonglong2*)&V[(kb + kk) * 32 + n0];
#pragma unroll
                for (int r = 0; r < 8; r++) {
                    float a = (kk == 0) ? av[r].x : (kk == 1) ? av[r].y : (kk == 2) ? av[r].z : av[r].w;
                    ull pa = dup2(a);
                    FMA2(acc[r][0], pa, bv.x);
                    FMA2(acc[r][1], pa, bv.y);
                }
            }
        }
#pragma unroll
        for (int r = 0; r < 8; r++) {
            *(ull*)&Tb[g * 4352 + (ty + 16 * r) * 34 + n0]     = acc[r][0];
            *(ull*)&Tb[g * 4352 + (ty + 16 * r) * 34 + n0 + 2] = acc[r][1];
        }
    }
    __syncthreads();

    // ---- Phase 3b: combine partials + U0, relu, write Z2T ----
    for (int m = 0; m < 8; m++) {
        int o = m * NTHREADS + tid;
        int i = o >> 5, h = o & 31;
        int base = i * 34 + h;
        float v = u0r[base] + Tb[base] + Tb[4352 + base] + Tb[8704 + base] + Tb[13056 + base];
        z2t[h * HWS + i] = fmaxf(v, 0.f);
    }
    __syncthreads();

    // ================= Phase 4: G = Z2@W1b (->sx1), P0 = Z2@W0b (->u0r) =================
    if (tid < 320) {
        const int f10 = tid >> 5;     // 0..9: 0-4 -> G, 5-9 -> P0
        const int kq  = tid & 31;
        const float* wv = (f10 < 5) ? (sw + 928) : (sw + 768);
        const int f = (f10 < 5) ? f10 : (f10 - 5);
        ull a0 = 0ull, a1 = 0ull;
#pragma unroll 8
        for (int h = 0; h < 32; h++) {
            ull pw = dup2(wv[h * 5 + f]);
            ulonglong2 zv = *(const ulonglong2*)&z2t[h * HWS + kq * 4];
            FMA2(a0, pw, zv.x);
            FMA2(a1, pw, zv.y);
        }
        float* dst = (f10 < 5) ? &sx1[f * 128 + kq * 4] : &u0r[f * 128 + kq * 4];
        *(ull*)&dst[0] = a0;
        *(ull*)&dst[2] = a1;
    }
    __syncthreads();

    // ================= Phase 5: partials of HW@G (j-split 4), k-paired =================
    {
        const int k = tid & 127, q = tid >> 7;
        const int jb = 32 * q;
        const float* hr = &HWs[k * HWS + jb];
        ull a2[5] = {0ull, 0ull, 0ull, 0ull, 0ull};
#pragma unroll 4
        for (int j = 0; j < 32; j += 4) {
            ulonglong2 h2v = *(const ulonglong2*)&hr[j];
#pragma unroll
            for (int f = 0; f < 5; f++) {
                ulonglong2 gv = *(const ulonglong2*)&sx1[f * 128 + jb + j];
                FMA2(a2[f], h2v.x, gv.x);
                FMA2(a2[f], h2v.y, gv.y);
            }
        }
#pragma unroll
        for (int f = 0; f < 5; f++)
            Tb[q * 640 + f * 128 + k] = hadd2(a2[f]);
    }
    __syncthreads();
    // x += P0 + HW@G
    for (int o = tid; o < 640; o += NTHREADS)
        xs[o] += u0r[o] + Tb[o] + Tb[640 + o] + Tb[1280 + o] + Tb[1920 + o];
    __syncthreads();

    // ================= band-0 sum =================
    if (tid < 32) {
        float s = xs[tid] + xs[tid + 32] + xs[tid + 64] + xs[tid + 96];
#pragma unroll
        for (int m = 16; m > 0; m >>= 1) s += __shfl_xor_sync(0xffffffffu, s, m);
        if (tid == 0) red[0] = s;
    }
    __syncthreads();

    // ================= projection + band clamps (fused) =================
    {
        float fproj = red[0] - 10.0f;
        float nu3 = gnu3[0], tg = gtg[0];
        float Vnu = 1.f - 1.f / ((1.f + nu3) * (1.f + nu3));
        float Vg  = 1.f - 1.f / ((1.f + tg) * (1.f + tg));
        for (int m = tid; m < 640; m += NTHREADS) {
            float v = xs[m];
            int band = m >> 7;
            if (band == 0 && fproj > 0.f) v -= fproj * (1.f / 128.f);
            v = fmaxf(v, band == 1 ? nu3 : 0.f);
            if (band == 2) v = fminf(v, tg);
            if (band == 3) v = fminf(fmaxf(v, Vnu), Vg);
            xs[m] = v;
        }
    }
    __syncthreads();

    // ================= outputs: x write + dacc partials =================
    {
        float* outx = out + (size_t)b * 640;
        for (int o = tid; o < 160; o += NTHREADS)
            *(float4*)&outx[o * 4] = *(const float4*)&xs[o * 4];
        const int k = tid & 127, q = tid >> 7;
        float acc = 0.f;
#pragma unroll 8
        for (int i = 32 * q; i < 32 * q + 32; i++)
            acc += xs[i] * HWs[i * HWS + k];
        Tb[q * 128 + k] = acc;
    }
    __syncthreads();
    {
        const size_t BM = (size_t)Bsz * 640;
        const size_t BK = (size_t)Bsz * 128;
        if (tid < 128) {
            int k = tid;
            float p  = xs[k];
            float nu = xs[128 + k];
            float xg = xs[256 + k];
            float xv = xs[384 + k];
            float s4 = xs[512 + k];
            float f5 = 1.f - 1.f / ((1.f + xg) * (1.f + xg)) - xv;
            float f6 = sqrtf(xv) - s4;
            float dacc = Tb[k] + Tb[128 + k] + Tb[256 + k] + Tb[384 + k];
            float top  = p * HWs[k * HWS + k];
            float down = dacc - top + 1.f;
            out[BM +            (size_t)b * 128 + k] = f5;
            out[BM +     BK +   (size_t)b * 128 + k] = f6;
            out[BM + 2 * BK +   (size_t)b * 128 + k] = top - down * xg;
            out[BM + 3 * BK +   (size_t)b * 128 + k] = nu * down - top;
        }
    }
}

extern "C" void kernel_launch(void* const* d_in, const int* in_sizes, int n_in,
                              void* d_out, int out_size) {
    const float* HW    = (const float*)d_in[2];
    const float* x0    = (const float*)d_in[3];
    const float* nu3   = (const float*)d_in[4];
    const float* tg    = (const float*)d_in[5];
    const float* g1W0a = (const float*)d_in[12];
    const float* g1W1a = (const float*)d_in[13];
    const float* g1W0b = (const float*)d_in[14];
    const float* g1W1b = (const float*)d_in[15];
    const float* g2W0a = (const float*)d_in[16];
    const float* g2W1a = (const float*)d_in[17];
    const float* g2W0b = (const float*)d_in[18];
    const float* g2W1b = (const float*)d_in[19];

    cudaFuncSetAttribute(unfold_pocs_kernel,
                         cudaFuncAttributeMaxDynamicSharedMemorySize,
                         SMEM_FLOATS * 4);

    unfold_pocs_kernel<<<Bsz, NTHREADS, SMEM_FLOATS * 4>>>(
        HW, x0, nu3, tg,
        g1W0a, g1W1a, g1W0b, g1W1b,
        g2W0a, g2W1a, g2W0b, g2W1b,
        (float*)d_out);
}

// round 7
// speedup vs baseline: 1.8149x; 1.0956x over previous
#include <cuda_runtime.h>
#include <math.h>
#include <stdint.h>

#define Bsz 2048
#define NTHREADS 512
#define HWS 132

typedef unsigned long long ull;

// ---- smem layout (float offsets) ----
#define O_HW   0        // 16896 : HW row-major stride 132
#define O_WB   16896    // 8704  : W64 B [k][68]  (later: phase-3 partials 2 x 4352, stride 34)
#define O_VB   25600    // 4608  : V   B [k][36]
#define O_T    30208    // 8448  : T [k][66] (later: phase5 partials + dacc partials)
#define O_XS   38656    // 640
#define O_SX1  39296    // 640 (later G)
#define O_U0   39936    // 4224 : GNN1 scratch -> U0 stride 33 -> P0 plain [0,640)
#define O_Z2   44160    // 4608 : z2 [k][36]
#define O_SW   48768    // 1088
#define O_CC   49856    // 128
#define O_RED  49984    // 64
#define SMEM_FLOATS 50048
#define SMEM_BYTES (SMEM_FLOATS * 4)

__device__ __forceinline__ ull dup2(float x) {
    ull r; asm("mov.b64 %0, {%1, %1};" : "=l"(r) : "f"(x)); return r;
}
#define FMA2(acc, a, b) asm("fma.rn.f32x2 %0, %1, %2, %0;" : "+l"(acc) : "l"(a), "l"(b))
__device__ __forceinline__ float hadd2(ull v) {
    float lo, hi; asm("mov.b64 {%0, %1}, %2;" : "=f"(lo), "=f"(hi) : "l"(v)); return lo + hi;
}
__device__ __forceinline__ void bar_grpB() {
    asm volatile("bar.sync 1, 256;" ::: "memory");
}
__device__ __forceinline__ void mma_tf32(float* c, const uint32_t* a, uint32_t b0, uint32_t b1) {
    asm volatile(
        "mma.sync.aligned.m16n8k8.row.col.f32.tf32.tf32.f32 "
        "{%0,%1,%2,%3}, {%4,%5,%6,%7}, {%8,%9}, {%0,%1,%2,%3};"
        : "+f"(c[0]), "+f"(c[1]), "+f"(c[2]), "+f"(c[3])
        : "r"(a[0]), "r"(a[1]), "r"(a[2]), "r"(a[3]), "r"(b0), "r"(b1));
}

__global__ __launch_bounds__(NTHREADS, 1)
void unfold_pocs_kernel(const float* __restrict__ gHW, const float* __restrict__ gx0,
                        const float* __restrict__ gnu3, const float* __restrict__ gtg,
                        const float* __restrict__ g1W0a, const float* __restrict__ g1W1a,
                        const float* __restrict__ g1W0b, const float* __restrict__ g1W1b,
                        const float* __restrict__ g2W0a, const float* __restrict__ g2W1a,
                        const float* __restrict__ g2W0b, const float* __restrict__ g2W1b,
                        float* __restrict__ out) {
    extern __shared__ float sm[];
    const int b = blockIdx.x;
    const int tid = threadIdx.x;
    const int wid = tid >> 5;
    const int lid = tid & 31;
    const int lr = lid >> 2;   // 0..7
    const int lc = lid & 3;    // 0..3

    float* HWs = sm + O_HW;
    float* WB  = sm + O_WB;
    float* VB  = sm + O_VB;
    float* Tb  = sm + O_T;
    float* xs  = sm + O_XS;
    float* sx1 = sm + O_SX1;
    float* u0r = sm + O_U0;
    float* z2s = sm + O_Z2;
    float* sw  = sm + O_SW;
    float* cC  = sm + O_CC;
    float* red = sm + O_RED;

    const float* hwg = gHW + (size_t)b * (128 * 128);

    // ================= Phase 0: loads =================
    for (int o = tid; o < 4096; o += NTHREADS) {
        float4 v = *(const float4*)(hwg + o * 4);
        int w = o * 4;
        int row = w >> 7, col = w & 127;
        *(float4*)&HWs[row * HWS + col] = v;
    }
    for (int o = tid; o < 160; o += NTHREADS)
        *(float4*)&xs[o * 4] = *(const float4*)(gx0 + (size_t)b * 640 + o * 4);
    for (int o = tid; o < 8192; o += NTHREADS) {
        int k = o >> 6, h = o & 63;
        WB[k * 68 + h] = (h < 32) ? g2W0a[k * 32 + h] : g2W1a[k * 32 + (h - 32)];
    }
    for (int o = tid; o < 160; o += NTHREADS) sw[o]       = g1W0a[o];
    for (int o = tid; o < 160; o += NTHREADS) sw[160 + o] = g1W1a[o];
    for (int o = tid; o < 64;  o += NTHREADS) sw[320 + o] = g1W0b[o];
    for (int o = tid; o < 64;  o += NTHREADS) sw[384 + o] = g1W1b[o];
    for (int o = tid; o < 160; o += NTHREADS) sw[448 + o] = g2W0a[128 * 32 + o];
    for (int o = tid; o < 160; o += NTHREADS) sw[608 + o] = g2W1a[128 * 32 + o];
    // packed transposed output weights: wp0[f*32+h] = W0b[h][f]
    for (int o = tid; o < 160; o += NTHREADS) {
        int f = o >> 5, h = o & 31;
        sw[768 + f * 32 + h] = g2W0b[h * 5 + f];
        sw[928 + f * 32 + h] = g2W1b[h * 5 + f];
    }
    __syncthreads();

    // ================= Phase 1: split =================
    if (wid < 8) {
        // ---- Group A: T = HW @ W64 via HMMA tf32 (each warp: 16 rows x 64 cols) ----
        const int m0 = wid * 16;
        float acc[8][4];
#pragma unroll
        for (int nt = 0; nt < 8; nt++)
#pragma unroll
            for (int c = 0; c < 4; c++) acc[nt][c] = 0.f;
#pragma unroll 2
        for (int k0 = 0; k0 < 128; k0 += 8) {
            uint32_t a[4];
            a[0] = __float_as_uint(HWs[(m0 + lr)     * HWS + k0 + lc]);
            a[1] = __float_as_uint(HWs[(m0 + lr + 8) * HWS + k0 + lc]);
            a[2] = __float_as_uint(HWs[(m0 + lr)     * HWS + k0 + lc + 4]);
            a[3] = __float_as_uint(HWs[(m0 + lr + 8) * HWS + k0 + lc + 4]);
#pragma unroll
            for (int nt = 0; nt < 8; nt++) {
                uint32_t b0 = __float_as_uint(WB[(k0 + lc)     * 68 + nt * 8 + lr]);
                uint32_t b1 = __float_as_uint(WB[(k0 + lc + 4) * 68 + nt * 8 + lr]);
                mma_tf32(acc[nt], a, b0, b1);
            }
        }
#pragma unroll
        for (int nt = 0; nt < 8; nt++) {
            *(float2*)&Tb[(m0 + lr)     * 66 + nt * 8 + 2 * lc] = make_float2(acc[nt][0], acc[nt][1]);
            *(float2*)&Tb[(m0 + lr + 8) * 66 + nt * 8 + 2 * lc] = make_float2(acc[nt][2], acc[nt][3]);
        }
    } else {
        // ---- Group B: GNN1 chain (warps 8-15) ----
        const int t2 = tid - 256;
        {   // SX1 partials: j-split 2
            const int i = t2 & 127, h2 = t2 >> 7;
            const int jb = 64 * h2;
            const float* hr = &HWs[i * HWS + jb];
            ull a2[5] = {0ull, 0ull, 0ull, 0ull, 0ull};
#pragma unroll 4
            for (int j = 0; j < 64; j += 4) {
                ulonglong2 h2v = *(const ulonglong2*)&hr[j];
#pragma unroll
                for (int f = 0; f < 5; f++) {
                    ulonglong2 xv = *(const ulonglong2*)&xs[f * 128 + jb + j];
                    FMA2(a2[f], h2v.x, xv.x);
                    FMA2(a2[f], h2v.y, xv.y);
                }
            }
#pragma unroll
            for (int f = 0; f < 5; f++)
                u0r[h2 * 640 + f * 128 + i] = hadd2(a2[f]);
        }
        if (t2 < 128) {
            float acc = 0.f;
#pragma unroll 4
            for (int i = 0; i < 128; i++) acc += HWs[i * HWS + t2];
            cC[t2] = acc * (1.f / 128.f);
        }
        bar_grpB();
        for (int o = t2; o < 640; o += 256) sx1[o] = u0r[o] + u0r[640 + o];
        bar_grpB();
        {   // Z1 = relu(X1@W0a + SX1@W1a) into u0r
            const float* w0a = sw;
            const float* w1a = sw + 160;
            for (int o = t2; o < 4096; o += 256) {
                int k = o >> 5, h = o & 31;
                float acc = 0.f;
#pragma unroll
                for (int f = 0; f < 5; f++)
                    acc += xs[f * 128 + k] * w0a[f * 32 + h] + sx1[f * 128 + k] * w1a[f * 32 + h];
                u0r[o] = fmaxf(acc, 0.f);
            }
        }
        bar_grpB();
        if (t2 < 32) {
            float m = 0.f, cz = 0.f;
#pragma unroll 4
            for (int k = 0; k < 128; k++) {
                float zv = u0r[k * 32 + t2];
                m += zv;
                cz += cC[k] * zv;
            }
            red[t2] = m * (1.f / 128.f);
            red[32 + t2] = cz;
        }
        bar_grpB();
        if (t2 < 2) {
            const float* w0b = sw + 320;
            const float* w1b = sw + 384;
            float acc = 0.f;
#pragma unroll 8
            for (int h = 0; h < 32; h++)
                acc += red[h] * w0b[h * 2 + t2] + red[32 + h] * w1b[h * 2 + t2];
            red[62 + t2] = fmaxf(acc, 0.f);   // lbd
        }
        bar_grpB();
        if (t2 < 128) {
            float l0 = red[62], l1 = red[63];
            float s1v = xs[128 + t2];
            xs[128 + t2] = s1v - l0 * ((1.0f / 128.f) / (1.f + s1v));
            xs[512 + t2] += l1 * ((1.0f / 128.f) * 0.1f);
        }
    }
    __syncthreads();

    // ================= Phase 2: U0 (stride 33) / V ([k][36]) =================
    {
        const float* w0bot = sw + 448;
        const float* w1bot = sw + 608;
        for (int o = tid; o < 4096; o += NTHREADS) {
            int k = o >> 5, h = o & 31;
            float u = Tb[k * 66 + h];
            float v = Tb[k * 66 + 32 + h];
#pragma unroll
            for (int f = 0; f < 5; f++) {
                float xv = xs[f * 128 + k];
                u += xv * w0bot[f * 32 + h];
                v += xv * w1bot[f * 32 + h];
            }
            u0r[k * 33 + h] = u;
            VB[k * 36 + h] = v;
        }
    }
    __syncthreads();

    // ================= Phase 3: HW@V via HMMA tf32, K-split 2 over 16 warps =================
    {
        float* P3 = sm + O_WB;   // W64 dead: 2 x (128*34) partial buffers
        const int w8 = wid & 7, kh = wid >> 3;
        const int m0 = w8 * 16;
        float acc[4][4];
#pragma unroll
        for (int nt = 0; nt < 4; nt++)
#pragma unroll
            for (int c = 0; c < 4; c++) acc[nt][c] = 0.f;
#pragma unroll 2
        for (int k0 = kh * 64; k0 < kh * 64 + 64; k0 += 8) {
            uint32_t a[4];
            a[0] = __float_as_uint(HWs[(m0 + lr)     * HWS + k0 + lc]);
            a[1] = __float_as_uint(HWs[(m0 + lr + 8) * HWS + k0 + lc]);
            a[2] = __float_as_uint(HWs[(m0 + lr)     * HWS + k0 + lc + 4]);
            a[3] = __float_as_uint(HWs[(m0 + lr + 8) * HWS + k0 + lc + 4]);
#pragma unroll
            for (int nt = 0; nt < 4; nt++) {
                uint32_t b0 = __float_as_uint(VB[(k0 + lc)     * 36 + nt * 8 + lr]);
                uint32_t b1 = __float_as_uint(VB[(k0 + lc + 4) * 36 + nt * 8 + lr]);
                mma_tf32(acc[nt], a, b0, b1);
            }
        }
        float* P = P3 + kh * 4352;
#pragma unroll
        for (int nt = 0; nt < 4; nt++) {
            *(float2*)&P[(m0 + lr)     * 34 + nt * 8 + 2 * lc] = make_float2(acc[nt][0], acc[nt][1]);
            *(float2*)&P[(m0 + lr + 8) * 34 + nt * 8 + 2 * lc] = make_float2(acc[nt][2], acc[nt][3]);
        }
    }
    __syncthreads();

    // ---- Phase 3b: z2 = relu(U0 + HW@V) -> z2s [k][36] ----
    {
        const float* P3 = sm + O_WB;
#pragma unroll
        for (int m = 0; m < 8; m++) {
            int o = m * NTHREADS + tid;
            int k = o >> 5, h = o & 31;
            z2s[k * 36 + h] = fmaxf(u0r[k * 33 + h] + P3[k * 34 + h] + P3[4352 + k * 34 + h], 0.f);
        }
    }
    __syncthreads();

    // ================= Phase 4: G = Z2@W1b (->sx1), P0 = Z2@W0b (->u0r plain) =================
    for (int o = tid; o < 640; o += NTHREADS) {
        int k = o & 127, f = o >> 7;
        const float* zr  = &z2s[k * 36];
        const float* wp0 = &sw[768 + f * 32];
        const float* wp1 = &sw[928 + f * 32];
        ull g2a = 0ull, p2a = 0ull;
#pragma unroll
        for (int h = 0; h < 32; h += 4) {
            ulonglong2 zv  = *(const ulonglong2*)&zr[h];
            ulonglong2 w1v = *(const ulonglong2*)&wp1[h];
            ulonglong2 w0v = *(const ulonglong2*)&wp0[h];
            FMA2(g2a, zv.x, w1v.x);
            FMA2(g2a, zv.y, w1v.y);
            FMA2(p2a, zv.x, w0v.x);
            FMA2(p2a, zv.y, w0v.y);
        }
        sx1[f * 128 + k] = hadd2(g2a);
        u0r[f * 128 + k] = hadd2(p2a);
    }
    __syncthreads();

    // ================= Phase 5: partials of HW@G (j-split 4) =================
    {
        const int k = tid & 127, q = tid >> 7;
        const int jb = 32 * q;
        const float* hr = &HWs[k * HWS + jb];
        ull a2[5] = {0ull, 0ull, 0ull, 0ull, 0ull};
#pragma unroll
        for (int j = 0; j < 32; j += 4) {
            ulonglong2 h2v = *(const ulonglong2*)&hr[j];
#pragma unroll
            for (int f = 0; f < 5; f++) {
                ulonglong2 gv = *(const ulonglong2*)&sx1[f * 128 + jb + j];
                FMA2(a2[f], h2v.x, gv.x);
                FMA2(a2[f], h2v.y, gv.y);
            }
        }
#pragma unroll
        for (int f = 0; f < 5; f++)
            Tb[q * 640 + f * 128 + k] = hadd2(a2[f]);
    }
    __syncthreads();
    for (int o = tid; o < 640; o += NTHREADS)
        xs[o] += u0r[o] + Tb[o] + Tb[640 + o] + Tb[1280 + o] + Tb[1920 + o];
    __syncthreads();

    // ================= band-0 sum =================
    if (tid < 32) {
        float s = xs[tid] + xs[tid + 32] + xs[tid + 64] + xs[tid + 96];
#pragma unroll
        for (int m = 16; m > 0; m >>= 1) s += __shfl_xor_sync(0xffffffffu, s, m);
        if (tid == 0) red[0] = s;
    }
    __syncthreads();

    // ================= projection + band clamps =================
    {
        float fproj = red[0] - 10.0f;
        float nu3 = gnu3[0], tg = gtg[0];
        float Vnu = 1.f - 1.f / ((1.f + nu3) * (1.f + nu3));
        float Vg  = 1.f - 1.f / ((1.f + tg) * (1.f + tg));
        for (int m = tid; m < 640; m += NTHREADS) {
            float v = xs[m];
            int band = m >> 7;
            if (band == 0 && fproj > 0.f) v -= fproj * (1.f / 128.f);
            v = fmaxf(v, band == 1 ? nu3 : 0.f);
            if (band == 2) v = fminf(v, tg);
            if (band == 3) v = fminf(fmaxf(v, Vnu), Vg);
            xs[m] = v;
        }
    }
    __syncthreads();

    // ================= outputs =================
    {
        float* outx = out + (size_t)b * 640;
        for (int o = tid; o < 160; o += NTHREADS)
            *(float4*)&outx[o * 4] = *(const float4*)&xs[o * 4];
        const int k = tid & 127, q = tid >> 7;
        float acc = 0.f;
#pragma unroll 8
        for (int i = 32 * q; i < 32 * q + 32; i++)
            acc += xs[i] * HWs[i * HWS + k];
        Tb[2560 + q * 128 + k] = acc;
    }
    __syncthreads();
    {
        const size_t BM = (size_t)Bsz * 640;
        const size_t BK = (size_t)Bsz * 128;
        if (tid < 128) {
            int k = tid;
            float p  = xs[k];
            float nu = xs[128 + k];
            float xg = xs[256 + k];
            float xv = xs[384 + k];
            float s4 = xs[512 + k];
            float f5 = 1.f - 1.f / ((1.f + xg) * (1.f + xg)) - xv;
            float f6 = sqrtf(xv) - s4;
            float dacc = Tb[2560 + k] + Tb[2688 + k] + Tb[2816 + k] + Tb[2944 + k];
            float top  = p * HWs[k * HWS + k];
            float down = dacc - top + 1.f;
            out[BM +            (size_t)b * 128 + k] = f5;
            out[BM +     BK +   (size_t)b * 128 + k] = f6;
            out[BM + 2 * BK +   (size_t)b * 128 + k] = top - down * xg;
            out[BM + 3 * BK +   (size_t)b * 128 + k] = nu * down - top;
        }
    }
}

extern "C" void kernel_launch(void* const* d_in, const int* in_sizes, int n_in,
                              void* d_out, int out_size) {
    const float* HW    = (const float*)d_in[2];
    const float* x0    = (const float*)d_in[3];
    const float* nu3   = (const float*)d_in[4];
    const float* tg    = (const float*)d_in[5];
    const float* g1W0a = (const float*)d_in[12];
    const float* g1W1a = (const float*)d_in[13];
    const float* g1W0b = (const float*)d_in[14];
    const float* g1W1b = (const float*)d_in[15];
    const float* g2W0a = (const float*)d_in[16];
    const float* g2W1a = (const float*)d_in[17];
    const float* g2W0b = (const float*)d_in[18];
    const float* g2W1b = (const float*)d_in[19];

    cudaFuncSetAttribute(unfold_pocs_kernel,
                         cudaFuncAttributeMaxDynamicSharedMemorySize, SMEM_BYTES);

    unfold_pocs_kernel<<<Bsz, NTHREADS, SMEM_BYTES>>>(
        HW, x0, nu3, tg,
        g1W0a, g1W1a, g1W0b, g1W1b,
        g2W0a, g2W1a, g2W0b, g2W1b,
        (float*)d_out);
}

// round 8
// speedup vs baseline: 2.1738x; 1.1978x over previous
#include <cuda_runtime.h>
#include <math.h>
#include <stdint.h>

#define Bsz 2048
#define NTHREADS 512
#define HWS 132

typedef unsigned long long ull;

// ---- smem layout (float offsets) ----
#define O_HW   0        // 16896 : HW row-major stride 132
#define O_WBF  16896    // 8192  : W64 fragment-ordered (later: phase5 partials 2560 + dacc 512)
#define O_VB   25088    // 4608  : V [k][36]
#define O_Z2   29696    // 4608  : z2 [k][36]
#define O_XS   34304    // 640
#define O_SX1  34944    // 640 (later G)
#define O_SC   35584    // 4224 : GNN1 scratch (SX1 partials, Z1) ; later P0 [0,640)
#define O_SW   39808    // 1088
#define O_CC   40896    // 128
#define O_RED  41024    // 64
#define SMEM_FLOATS 41088
#define SMEM_BYTES (SMEM_FLOATS * 4)

__device__ __forceinline__ ull dup2(float x) {
    ull r; asm("mov.b64 %0, {%1, %1};" : "=l"(r) : "f"(x)); return r;
}
#define FMA2(acc, a, b) asm("fma.rn.f32x2 %0, %1, %2, %0;" : "+l"(acc) : "l"(a), "l"(b))
__device__ __forceinline__ float hadd2(ull v) {
    float lo, hi; asm("mov.b64 {%0, %1}, %2;" : "=f"(lo), "=f"(hi) : "l"(v)); return lo + hi;
}
__device__ __forceinline__ void bar_grpB() {
    asm volatile("bar.sync 1, 256;" ::: "memory");
}
__device__ __forceinline__ void bar_grpA() {
    asm volatile("bar.sync 2, 256;" ::: "memory");
}
__device__ __forceinline__ void mma_tf32(float* c, const uint32_t* a, uint32_t b0, uint32_t b1) {
    asm volatile(
        "mma.sync.aligned.m16n8k8.row.col.f32.tf32.tf32.f32 "
        "{%0,%1,%2,%3}, {%4,%5,%6,%7}, {%8,%9}, {%0,%1,%2,%3};"
        : "+f"(c[0]), "+f"(c[1]), "+f"(c[2]), "+f"(c[3])
        : "r"(a[0]), "r"(a[1]), "r"(a[2]), "r"(a[3]), "r"(b0), "r"(b1));
}

__global__ __launch_bounds__(NTHREADS, 1)
void unfold_pocs_kernel(const float* __restrict__ gHW, const float* __restrict__ gx0,
                        const float* __restrict__ gnu3, const float* __restrict__ gtg,
                        const float* __restrict__ g1W0a, const float* __restrict__ g1W1a,
                        const float* __restrict__ g1W0b, const float* __restrict__ g1W1b,
                        const float* __restrict__ g2W0a, const float* __restrict__ g2W1a,
                        const float* __restrict__ g2W0b, const float* __restrict__ g2W1b,
                        float* __restrict__ out) {
    extern __shared__ float sm[];
    const int b = blockIdx.x;
    const int tid = threadIdx.x;
    const int wid = tid >> 5;
    const int lid = tid & 31;
    const int lr = lid >> 2;   // 0..7
    const int lc = lid & 3;    // 0..3

    float* HWs = sm + O_HW;
    float* WBF = sm + O_WBF;
    float* VB  = sm + O_VB;
    float* z2s = sm + O_Z2;
    float* xs  = sm + O_XS;
    float* sx1 = sm + O_SX1;
    float* scr = sm + O_SC;
    float* sw  = sm + O_SW;
    float* cC  = sm + O_CC;
    float* red = sm + O_RED;

    const float* hwg = gHW + (size_t)b * (128 * 128);

    // ================= Phase 0: loads =================
    for (int o = tid; o < 4096; o += NTHREADS) {
        float4 v = *(const float4*)(hwg + o * 4);
        int w = o * 4;
        int row = w >> 7, col = w & 127;
        *(float4*)&HWs[row * HWS + col] = v;
    }
    for (int o = tid; o < 160; o += NTHREADS)
        *(float4*)&xs[o * 4] = *(const float4*)(gx0 + (size_t)b * 640 + o * 4);
    // W64 fragment-ordered: element (k, h) -> chunk (k>>4), ntile (h>>3),
    // lane (h&7)*4+(k&3), component (k>>2)&3
    for (int o = tid; o < 8192; o += NTHREADS) {
        int k = o >> 6, h = o & 63;
        float v = (h < 32) ? g2W0a[k * 32 + h] : g2W1a[k * 32 + (h - 32)];
        int pos = (((k >> 4) * 8 + (h >> 3)) << 7) + (((h & 7) * 4 + (k & 3)) << 2) + ((k >> 2) & 3);
        WBF[pos] = v;
    }
    for (int o = tid; o < 160; o += NTHREADS) sw[o]       = g1W0a[o];
    for (int o = tid; o < 160; o += NTHREADS) sw[160 + o] = g1W1a[o];
    for (int o = tid; o < 64;  o += NTHREADS) sw[320 + o] = g1W0b[o];
    for (int o = tid; o < 64;  o += NTHREADS) sw[384 + o] = g1W1b[o];
    for (int o = tid; o < 160; o += NTHREADS) sw[448 + o] = g2W0a[128 * 32 + o];
    for (int o = tid; o < 160; o += NTHREADS) sw[608 + o] = g2W1a[128 * 32 + o];
    for (int o = tid; o < 160; o += NTHREADS) {
        int f = o >> 5, h = o & 31;
        sw[768 + f * 32 + h] = g2W0b[h * 5 + f];
        sw[928 + f * 32 + h] = g2W1b[h * 5 + f];
    }
    __syncthreads();

    float acc[8][4];     // group A: T fragments, then U0 in acc[0..3]
    float acc2[4][4];    // group A: HW@V fragments
    const int m0 = (wid & 7) * 16;

    // ================= Phase 1: split =================
    if (wid < 8) {
        // ---- Group A: T = HW @ W64 via HMMA tf32 ----
#pragma unroll
        for (int nt = 0; nt < 8; nt++)
#pragma unroll
            for (int c = 0; c < 4; c++) acc[nt][c] = 0.f;
#pragma unroll
        for (int kc = 0; kc < 8; kc++) {
            const int k0 = kc * 16;
            uint32_t a0[4], a1[4];
            a0[0] = __float_as_uint(HWs[(m0 + lr)     * HWS + k0 + lc]);
            a0[1] = __float_as_uint(HWs[(m0 + lr + 8) * HWS + k0 + lc]);
            a0[2] = __float_as_uint(HWs[(m0 + lr)     * HWS + k0 + lc + 4]);
            a0[3] = __float_as_uint(HWs[(m0 + lr + 8) * HWS + k0 + lc + 4]);
            a1[0] = __float_as_uint(HWs[(m0 + lr)     * HWS + k0 + 8 + lc]);
            a1[1] = __float_as_uint(HWs[(m0 + lr + 8) * HWS + k0 + 8 + lc]);
            a1[2] = __float_as_uint(HWs[(m0 + lr)     * HWS + k0 + 12 + lc]);
            a1[3] = __float_as_uint(HWs[(m0 + lr + 8) * HWS + k0 + 12 + lc]);
#pragma unroll
            for (int nt = 0; nt < 8; nt++) {
                float4 bv = *(const float4*)&WBF[((kc << 3) + nt) << 7 | (lid << 2)];
                mma_tf32(acc[nt], a0, __float_as_uint(bv.x), __float_as_uint(bv.y));
                mma_tf32(acc[nt], a1, __float_as_uint(bv.z), __float_as_uint(bv.w));
            }
        }
    } else {
        // ---- Group B: GNN1 chain (warps 8-15) ----
        const int t2 = tid - 256;
        {   // SX1 partials: j-split 2
            const int i = t2 & 127, h2 = t2 >> 7;
            const int jb = 64 * h2;
            const float* hr = &HWs[i * HWS + jb];
            ull a2[5] = {0ull, 0ull, 0ull, 0ull, 0ull};
#pragma unroll 4
            for (int j = 0; j < 64; j += 4) {
                ulonglong2 h2v = *(const ulonglong2*)&hr[j];
#pragma unroll
                for (int f = 0; f < 5; f++) {
                    ulonglong2 xv = *(const ulonglong2*)&xs[f * 128 + jb + j];
                    FMA2(a2[f], h2v.x, xv.x);
                    FMA2(a2[f], h2v.y, xv.y);
                }
            }
#pragma unroll
            for (int f = 0; f < 5; f++)
                scr[h2 * 640 + f * 128 + i] = hadd2(a2[f]);
        }
        if (t2 < 128) {
            float a = 0.f;
#pragma unroll 4
            for (int i = 0; i < 128; i++) a += HWs[i * HWS + t2];
            cC[t2] = a * (1.f / 128.f);
        }
        bar_grpB();
        for (int o = t2; o < 640; o += 256) sx1[o] = scr[o] + scr[640 + o];
        bar_grpB();
        {   // Z1 = relu(X1@W0a + SX1@W1a) into scr [k*32+h]
            const float* w0a = sw;
            const float* w1a = sw + 160;
            for (int o = t2; o < 4096; o += 256) {
                int k = o >> 5, h = o & 31;
                float a = 0.f;
#pragma unroll
                for (int f = 0; f < 5; f++)
                    a += xs[f * 128 + k] * w0a[f * 32 + h] + sx1[f * 128 + k] * w1a[f * 32 + h];
                scr[o] = fmaxf(a, 0.f);
            }
        }
        bar_grpB();
        if (t2 < 32) {
            float m = 0.f, cz = 0.f;
#pragma unroll 4
            for (int k = 0; k < 128; k++) {
                float zv = scr[k * 32 + t2];
                m += zv;
                cz += cC[k] * zv;
            }
            red[t2] = m * (1.f / 128.f);
            red[32 + t2] = cz;
        }
        bar_grpB();
        if (t2 < 2) {
            const float* w0b = sw + 320;
            const float* w1b = sw + 384;
            float a = 0.f;
#pragma unroll 8
            for (int h = 0; h < 32; h++)
                a += red[h] * w0b[h * 2 + t2] + red[32 + h] * w1b[h * 2 + t2];
            red[62 + t2] = fmaxf(a, 0.f);   // lbd
        }
        bar_grpB();
        if (t2 < 128) {
            float l0 = red[62], l1 = red[63];
            float s1v = xs[128 + t2];
            xs[128 + t2] = s1v - l0 * ((1.0f / 128.f) / (1.f + s1v));
            xs[512 + t2] += l1 * ((1.0f / 128.f) * 0.1f);
        }
    }
    __syncthreads();   // xs final; T in group-A regs

    // ================= Phase 2+3 (group A only): U0/V in regs, HMMA HW@V, z2 =================
    if (wid < 8) {
        const float* w0bot = sw + 448;
        const float* w1bot = sw + 608;
        float xr[2][5];
#pragma unroll
        for (int f = 0; f < 5; f++) {
            xr[0][f] = xs[f * 128 + m0 + lr];
            xr[1][f] = xs[f * 128 + m0 + lr + 8];
        }
#pragma unroll
        for (int nt = 0; nt < 8; nt++) {
            const bool isU = nt < 4;
            const float* wb = isU ? w0bot : w1bot;
            const int hb = (isU ? nt : nt - 4) * 8 + 2 * lc;
            float r00 = acc[nt][0], r01 = acc[nt][1];
            float r10 = acc[nt][2], r11 = acc[nt][3];
#pragma unroll
            for (int f = 0; f < 5; f++) {
                float w0 = wb[f * 32 + hb], w1 = wb[f * 32 + hb + 1];
                r00 += xr[0][f] * w0; r01 += xr[0][f] * w1;
                r10 += xr[1][f] * w0; r11 += xr[1][f] * w1;
            }
            if (isU) {
                acc[nt][0] = r00; acc[nt][1] = r01; acc[nt][2] = r10; acc[nt][3] = r11;
            } else {
                *(float2*)&VB[(m0 + lr)     * 36 + hb] = make_float2(r00, r01);
                *(float2*)&VB[(m0 + lr + 8) * 36 + hb] = make_float2(r10, r11);
            }
        }
        bar_grpA();   // V fully written by all 8 warps

        // HW @ V full-K (16 k-steps x 4 n-tiles)
#pragma unroll
        for (int nt = 0; nt < 4; nt++)
#pragma unroll
            for (int c = 0; c < 4; c++) acc2[nt][c] = 0.f;
#pragma unroll 4
        for (int ks = 0; ks < 16; ks++) {
            const int k0 = ks * 8;
            uint32_t a[4];
            a[0] = __float_as_uint(HWs[(m0 + lr)     * HWS + k0 + lc]);
            a[1] = __float_as_uint(HWs[(m0 + lr + 8) * HWS + k0 + lc]);
            a[2] = __float_as_uint(HWs[(m0 + lr)     * HWS + k0 + lc + 4]);
            a[3] = __float_as_uint(HWs[(m0 + lr + 8) * HWS + k0 + lc + 4]);
#pragma unroll
            for (int nt = 0; nt < 4; nt++) {
                uint32_t b0 = __float_as_uint(VB[(k0 + lc)     * 36 + nt * 8 + lr]);
                uint32_t b1 = __float_as_uint(VB[(k0 + lc + 4) * 36 + nt * 8 + lr]);
                mma_tf32(acc2[nt], a, b0, b1);
            }
        }
        // z2 = relu(U0 + HW@V)
#pragma unroll
        for (int nt = 0; nt < 4; nt++) {
            const int hb = nt * 8 + 2 * lc;
            *(float2*)&z2s[(m0 + lr) * 36 + hb] =
                make_float2(fmaxf(acc[nt][0] + acc2[nt][0], 0.f),
                            fmaxf(acc[nt][1] + acc2[nt][1], 0.f));
            *(float2*)&z2s[(m0 + lr + 8) * 36 + hb] =
                make_float2(fmaxf(acc[nt][2] + acc2[nt][2], 0.f),
                            fmaxf(acc[nt][3] + acc2[nt][3], 0.f));
        }
    }
    __syncthreads();

    // ================= Phase 4: G = Z2@W1b (->sx1), P0 = Z2@W0b (->scr) =================
    for (int o = tid; o < 640; o += NTHREADS) {
        int k = o & 127, f = o >> 7;
        const float* zr  = &z2s[k * 36];
        const float* wp0 = &sw[768 + f * 32];
        const float* wp1 = &sw[928 + f * 32];
        ull g2a = 0ull, p2a = 0ull;
#pragma unroll
        for (int h = 0; h < 32; h += 4) {
            ulonglong2 zv  = *(const ulonglong2*)&zr[h];
            ulonglong2 w1v = *(const ulonglong2*)&wp1[h];
            ulonglong2 w0v = *(const ulonglong2*)&wp0[h];
            FMA2(g2a, zv.x, w1v.x);
            FMA2(g2a, zv.y, w1v.y);
            FMA2(p2a, zv.x, w0v.x);
            FMA2(p2a, zv.y, w0v.y);
        }
        sx1[f * 128 + k] = hadd2(g2a);
        scr[f * 128 + k] = hadd2(p2a);
    }
    __syncthreads();

    // ================= Phase 5: partials of HW@G (j-split 4) -> WBF region =================
    {
        float* P5 = WBF;
        const int k = tid & 127, q = tid >> 7;
        const int jb = 32 * q;
        const float* hr = &HWs[k * HWS + jb];
        ull a2[5] = {0ull, 0ull, 0ull, 0ull, 0ull};
#pragma unroll
        for (int j = 0; j < 32; j += 4) {
            ulonglong2 h2v = *(const ulonglong2*)&hr[j];
#pragma unroll
            for (int f = 0; f < 5; f++) {
                ulonglong2 gv = *(const ulonglong2*)&sx1[f * 128 + jb + j];
                FMA2(a2[f], h2v.x, gv.x);
                FMA2(a2[f], h2v.y, gv.y);
            }
        }
#pragma unroll
        for (int f = 0; f < 5; f++)
            P5[q * 640 + f * 128 + k] = hadd2(a2[f]);
    }
    __syncthreads();
    for (int o = tid; o < 640; o += NTHREADS)
        xs[o] += scr[o] + WBF[o] + WBF[640 + o] + WBF[1280 + o] + WBF[1920 + o];
    __syncthreads();

    // ================= band-0 sum =================
    if (tid < 32) {
        float s = xs[tid] + xs[tid + 32] + xs[tid + 64] + xs[tid + 96];
#pragma unroll
        for (int m = 16; m > 0; m >>= 1) s += __shfl_xor_sync(0xffffffffu, s, m);
        if (tid == 0) red[0] = s;
    }
    __syncthreads();

    // ================= projection + band clamps =================
    {
        float fproj = red[0] - 10.0f;
        float nu3 = gnu3[0], tg = gtg[0];
        float Vnu = 1.f - 1.f / ((1.f + nu3) * (1.f + nu3));
        float Vg  = 1.f - 1.f / ((1.f + tg) * (1.f + tg));
        for (int m = tid; m < 640; m += NTHREADS) {
            float v = xs[m];
            int band = m >> 7;
            if (band == 0 && fproj > 0.f) v -= fproj * (1.f / 128.f);
            v = fmaxf(v, band == 1 ? nu3 : 0.f);
            if (band == 2) v = fminf(v, tg);
            if (band == 3) v = fminf(fmaxf(v, Vnu), Vg);
            xs[m] = v;
        }
    }
    __syncthreads();

    // ================= outputs =================
    {
        float* outx = out + (size_t)b * 640;
        for (int o = tid; o < 160; o += NTHREADS)
            *(float4*)&outx[o * 4] = *(const float4*)&xs[o * 4];
        const int k = tid & 127, q = tid >> 7;
        float a = 0.f;
#pragma unroll 8
        for (int i = 32 * q; i < 32 * q + 32; i++)
            a += xs[i] * HWs[i * HWS + k];
        WBF[2560 + q * 128 + k] = a;
    }
    __syncthreads();
    {
        const size_t BM = (size_t)Bsz * 640;
        const size_t BK = (size_t)Bsz * 128;
        if (tid < 128) {
            int k = tid;
            float p  = xs[k];
            float nu = xs[128 + k];
            float xg = xs[256 + k];
            float xv = xs[384 + k];
            float s4 = xs[512 + k];
            float f5 = 1.f - 1.f / ((1.f + xg) * (1.f + xg)) - xv;
            float f6 = sqrtf(xv) - s4;
            float dacc = WBF[2560 + k] + WBF[2688 + k] + WBF[2816 + k] + WBF[2944 + k];
            float top  = p * HWs[k * HWS + k];
            float down = dacc - top + 1.f;
            out[BM +            (size_t)b * 128 + k] = f5;
            out[BM +     BK +   (size_t)b * 128 + k] = f6;
            out[BM + 2 * BK +   (size_t)b * 128 + k] = top - down * xg;
            out[BM + 3 * BK +   (size_t)b * 128 + k] = nu * down - top;
        }
    }
}

extern "C" void kernel_launch(void* const* d_in, const int* in_sizes, int n_in,
                              void* d_out, int out_size) {
    const float* HW    = (const float*)d_in[2];
    const float* x0    = (const float*)d_in[3];
    const float* nu3   = (const float*)d_in[4];
    const float* tg    = (const float*)d_in[5];
    const float* g1W0a = (const float*)d_in[12];
    const float* g1W1a = (const float*)d_in[13];
    const float* g1W0b = (const float*)d_in[14];
    const float* g1W1b = (const float*)d_in[15];
    const float* g2W0a = (const float*)d_in[16];
    const float* g2W1a = (const float*)d_in[17];
    const float* g2W0b = (const float*)d_in[18];
    const float* g2W1b = (const float*)d_in[19];

    cudaFuncSetAttribute(unfold_pocs_kernel,
                         cudaFuncAttributeMaxDynamicSharedMemorySize, SMEM_BYTES);

    unfold_pocs_kernel<<<Bsz, NTHREADS, SMEM_BYTES>>>(
        HW, x0, nu3, tg,
        g1W0a, g1W1a, g1W0b, g1W1b,
        g2W0a, g2W1a, g2W0b, g2W1b,
        (float*)d_out);
}

// round 9
// speedup vs baseline: 2.6608x; 1.2240x over previous
#include <cuda_runtime.h>
#include <math.h>
#include <stdint.h>

#define Bsz 2048
#define NTHREADS 256
#define HWS 132

typedef unsigned long long ull;

// ---- smem layout (float offsets) ----
#define O_HW   0        // 16896 : HW row-major stride 132
#define O_U    16896    // 9216 union region:
                        //   phase1 : WBF (W64 fragment-ordered) 8192  @ U+0
                        //   GNN1   : scr (SX1 partials 1280 -> Z1 4096) @ U+0
                        //   phase2/3: VB [k][36] 4608 @ U+0 ; z2 [k][36] 4608 @ U+4608
                        //   phase4/5: P0 640 @ U+0 ; P5 1280 @ U+640 ; dacc 256 @ U+1920
#define O_XS   26112    // 640
#define O_SX1  26752    // 640 (later G)
#define O_SW   27392    // 1088
#define O_CC   28480    // 128
#define O_RED  28608    // 64
#define SMEM_FLOATS 28672
#define SMEM_BYTES (SMEM_FLOATS * 4)   // 114688 B -> 2 CTAs/SM

__device__ __forceinline__ ull dup2(float x) {
    ull r; asm("mov.b64 %0, {%1, %1};" : "=l"(r) : "f"(x)); return r;
}
#define FMA2(acc, a, b) asm("fma.rn.f32x2 %0, %1, %2, %0;" : "+l"(acc) : "l"(a), "l"(b))
__device__ __forceinline__ float hadd2(ull v) {
    float lo, hi; asm("mov.b64 {%0, %1}, %2;" : "=f"(lo), "=f"(hi) : "l"(v)); return lo + hi;
}
__device__ __forceinline__ void mma_tf32(float* c, const uint32_t* a, uint32_t b0, uint32_t b1) {
    asm volatile(
        "mma.sync.aligned.m16n8k8.row.col.f32.tf32.tf32.f32 "
        "{%0,%1,%2,%3}, {%4,%5,%6,%7}, {%8,%9}, {%0,%1,%2,%3};"
        : "+f"(c[0]), "+f"(c[1]), "+f"(c[2]), "+f"(c[3])
        : "r"(a[0]), "r"(a[1]), "r"(a[2]), "r"(a[3]), "r"(b0), "r"(b1));
}

__global__ __launch_bounds__(NTHREADS, 2)
void unfold_pocs_kernel(const float* __restrict__ gHW, const float* __restrict__ gx0,
                        const float* __restrict__ gnu3, const float* __restrict__ gtg,
                        const float* __restrict__ g1W0a, const float* __restrict__ g1W1a,
                        const float* __restrict__ g1W0b, const float* __restrict__ g1W1b,
                        const float* __restrict__ g2W0a, const float* __restrict__ g2W1a,
                        const float* __restrict__ g2W0b, const float* __restrict__ g2W1b,
                        float* __restrict__ out) {
    extern __shared__ float sm[];
    const int b = blockIdx.x;
    const int tid = threadIdx.x;
    const int wid = tid >> 5;
    const int lid = tid & 31;
    const int lr = lid >> 2;   // 0..7
    const int lc = lid & 3;    // 0..3

    float* HWs = sm + O_HW;
    float* U   = sm + O_U;
    float* xs  = sm + O_XS;
    float* sx1 = sm + O_SX1;
    float* sw  = sm + O_SW;
    float* cC  = sm + O_CC;
    float* red = sm + O_RED;

    const float* hwg = gHW + (size_t)b * (128 * 128);

    // ================= Phase 0: loads =================
    for (int o = tid; o < 4096; o += NTHREADS) {
        float4 v = *(const float4*)(hwg + o * 4);
        int w = o * 4;
        int row = w >> 7, col = w & 127;
        *(float4*)&HWs[row * HWS + col] = v;
    }
    for (int o = tid; o < 160; o += NTHREADS)
        *(float4*)&xs[o * 4] = *(const float4*)(gx0 + (size_t)b * 640 + o * 4);
    // W64 fragment-ordered into U+0
    for (int o = tid; o < 8192; o += NTHREADS) {
        int k = o >> 6, h = o & 63;
        float v = (h < 32) ? g2W0a[k * 32 + h] : g2W1a[k * 32 + (h - 32)];
        int pos = (((k >> 4) * 8 + (h >> 3)) << 7) + (((h & 7) * 4 + (k & 3)) << 2) + ((k >> 2) & 3);
        U[pos] = v;
    }
    for (int o = tid; o < 160; o += NTHREADS) sw[o]       = g1W0a[o];
    for (int o = tid; o < 160; o += NTHREADS) sw[160 + o] = g1W1a[o];
    for (int o = tid; o < 64;  o += NTHREADS) sw[320 + o] = g1W0b[o];
    for (int o = tid; o < 64;  o += NTHREADS) sw[384 + o] = g1W1b[o];
    for (int o = tid; o < 160; o += NTHREADS) sw[448 + o] = g2W0a[128 * 32 + o];
    for (int o = tid; o < 160; o += NTHREADS) sw[608 + o] = g2W1a[128 * 32 + o];
    for (int o = tid; o < 160; o += NTHREADS) {
        int f = o >> 5, h = o & 31;
        sw[768 + f * 32 + h] = g2W0b[h * 5 + f];
        sw[928 + f * 32 + h] = g2W1b[h * 5 + f];
    }
    __syncthreads();

    float acc[8][4];     // T fragments, then U0 in acc[0..3]
    float acc2[4][4];    // HW@V fragments
    const int m0 = wid * 16;

    // ================= Phase 1: T = HW @ W64 via HMMA tf32 (all 8 warps) ===========
    {
        const float* WBF = U;
#pragma unroll
        for (int nt = 0; nt < 8; nt++)
#pragma unroll
            for (int c = 0; c < 4; c++) acc[nt][c] = 0.f;
#pragma unroll
        for (int kc = 0; kc < 8; kc++) {
            const int k0 = kc * 16;
            uint32_t a0[4], a1[4];
            a0[0] = __float_as_uint(HWs[(m0 + lr)     * HWS + k0 + lc]);
            a0[1] = __float_as_uint(HWs[(m0 + lr + 8) * HWS + k0 + lc]);
            a0[2] = __float_as_uint(HWs[(m0 + lr)     * HWS + k0 + lc + 4]);
            a0[3] = __float_as_uint(HWs[(m0 + lr + 8) * HWS + k0 + lc + 4]);
            a1[0] = __float_as_uint(HWs[(m0 + lr)     * HWS + k0 + 8 + lc]);
            a1[1] = __float_as_uint(HWs[(m0 + lr + 8) * HWS + k0 + 8 + lc]);
            a1[2] = __float_as_uint(HWs[(m0 + lr)     * HWS + k0 + 12 + lc]);
            a1[3] = __float_as_uint(HWs[(m0 + lr + 8) * HWS + k0 + 12 + lc]);
#pragma unroll
            for (int nt = 0; nt < 8; nt++) {
                float4 bv = *(const float4*)&WBF[((kc << 3) + nt) << 7 | (lid << 2)];
                mma_tf32(acc[nt], a0, __float_as_uint(bv.x), __float_as_uint(bv.y));
                mma_tf32(acc[nt], a1, __float_as_uint(bv.z), __float_as_uint(bv.w));
            }
        }
    }
    __syncthreads();   // WBF dead; U becomes GNN1 scratch

    // ================= GNN1 chain (all 256 threads, T held in regs) =================
    {
        float* scr = U;
        {   // SX1 partials: j-split 2
            const int i = tid & 127, h2 = tid >> 7;
            const int jb = 64 * h2;
            const float* hr = &HWs[i * HWS + jb];
            ull a2[5] = {0ull, 0ull, 0ull, 0ull, 0ull};
#pragma unroll 4
            for (int j = 0; j < 64; j += 4) {
                ulonglong2 h2v = *(const ulonglong2*)&hr[j];
#pragma unroll
                for (int f = 0; f < 5; f++) {
                    ulonglong2 xv = *(const ulonglong2*)&xs[f * 128 + jb + j];
                    FMA2(a2[f], h2v.x, xv.x);
                    FMA2(a2[f], h2v.y, xv.y);
                }
            }
#pragma unroll
            for (int f = 0; f < 5; f++)
                scr[h2 * 640 + f * 128 + i] = hadd2(a2[f]);
        }
        if (tid < 128) {
            float a = 0.f;
#pragma unroll 4
            for (int i = 0; i < 128; i++) a += HWs[i * HWS + tid];
            cC[tid] = a * (1.f / 128.f);
        }
        __syncthreads();
        for (int o = tid; o < 640; o += NTHREADS) sx1[o] = scr[o] + scr[640 + o];
        __syncthreads();
        {   // Z1 = relu(X1@W0a + SX1@W1a) into scr [k*32+h]
            const float* w0a = sw;
            const float* w1a = sw + 160;
            for (int o = tid; o < 4096; o += NTHREADS) {
                int k = o >> 5, h = o & 31;
                float a = 0.f;
#pragma unroll
                for (int f = 0; f < 5; f++)
                    a += xs[f * 128 + k] * w0a[f * 32 + h] + sx1[f * 128 + k] * w1a[f * 32 + h];
                scr[o] = fmaxf(a, 0.f);
            }
        }
        __syncthreads();
        if (tid < 32) {
            float m = 0.f, cz = 0.f;
#pragma unroll 4
            for (int k = 0; k < 128; k++) {
                float zv = scr[k * 32 + tid];
                m += zv;
                cz += cC[k] * zv;
            }
            red[tid] = m * (1.f / 128.f);
            red[32 + tid] = cz;
        }
        __syncthreads();
        if (tid < 2) {
            const float* w0b = sw + 320;
            const float* w1b = sw + 384;
            float a = 0.f;
#pragma unroll 8
            for (int h = 0; h < 32; h++)
                a += red[h] * w0b[h * 2 + tid] + red[32 + h] * w1b[h * 2 + tid];
            red[62 + tid] = fmaxf(a, 0.f);   // lbd
        }
        __syncthreads();
        if (tid < 128) {
            float l0 = red[62], l1 = red[63];
            float s1v = xs[128 + tid];
            xs[128 + tid] = s1v - l0 * ((1.0f / 128.f) / (1.f + s1v));
            xs[512 + tid] += l1 * ((1.0f / 128.f) * 0.1f);
        }
    }
    __syncthreads();   // xs final; scr dead -> U becomes VB/z2

    // ================= Phase 2+3: U0/V in regs, HMMA HW@V, z2 =================
    {
        float* VB  = U;
        float* z2s = U + 4608;
        const float* w0bot = sw + 448;
        const float* w1bot = sw + 608;
        float xr[2][5];
#pragma unroll
        for (int f = 0; f < 5; f++) {
            xr[0][f] = xs[f * 128 + m0 + lr];
            xr[1][f] = xs[f * 128 + m0 + lr + 8];
        }
#pragma unroll
        for (int nt = 0; nt < 8; nt++) {
            const bool isU = nt < 4;
            const float* wb = isU ? w0bot : w1bot;
            const int hb = (isU ? nt : nt - 4) * 8 + 2 * lc;
            float r00 = acc[nt][0], r01 = acc[nt][1];
            float r10 = acc[nt][2], r11 = acc[nt][3];
#pragma unroll
            for (int f = 0; f < 5; f++) {
                float w0 = wb[f * 32 + hb], w1 = wb[f * 32 + hb + 1];
                r00 += xr[0][f] * w0; r01 += xr[0][f] * w1;
                r10 += xr[1][f] * w0; r11 += xr[1][f] * w1;
            }
            if (isU) {
                acc[nt][0] = r00; acc[nt][1] = r01; acc[nt][2] = r10; acc[nt][3] = r11;
            } else {
                *(float2*)&VB[(m0 + lr)     * 36 + hb] = make_float2(r00, r01);
                *(float2*)&VB[(m0 + lr + 8) * 36 + hb] = make_float2(r10, r11);
            }
        }
        __syncthreads();   // V fully written

        // HW @ V full-K
#pragma unroll
        for (int nt = 0; nt < 4; nt++)
#pragma unroll
            for (int c = 0; c < 4; c++) acc2[nt][c] = 0.f;
#pragma unroll 4
        for (int ks = 0; ks < 16; ks++) {
            const int k0 = ks * 8;
            uint32_t a[4];
            a[0] = __float_as_uint(HWs[(m0 + lr)     * HWS + k0 + lc]);
            a[1] = __float_as_uint(HWs[(m0 + lr + 8) * HWS + k0 + lc]);
            a[2] = __float_as_uint(HWs[(m0 + lr)     * HWS + k0 + lc + 4]);
            a[3] = __float_as_uint(HWs[(m0 + lr + 8) * HWS + k0 + lc + 4]);
#pragma unroll
            for (int nt = 0; nt < 4; nt++) {
                uint32_t b0 = __float_as_uint(VB[(k0 + lc)     * 36 + nt * 8 + lr]);
                uint32_t b1 = __float_as_uint(VB[(k0 + lc + 4) * 36 + nt * 8 + lr]);
                mma_tf32(acc2[nt], a, b0, b1);
            }
        }
        // z2 = relu(U0 + HW@V)
#pragma unroll
        for (int nt = 0; nt < 4; nt++) {
            const int hb = nt * 8 + 2 * lc;
            *(float2*)&z2s[(m0 + lr) * 36 + hb] =
                make_float2(fmaxf(acc[nt][0] + acc2[nt][0], 0.f),
                            fmaxf(acc[nt][1] + acc2[nt][1], 0.f));
            *(float2*)&z2s[(m0 + lr + 8) * 36 + hb] =
                make_float2(fmaxf(acc[nt][2] + acc2[nt][2], 0.f),
                            fmaxf(acc[nt][3] + acc2[nt][3], 0.f));
        }
    }
    __syncthreads();

    // ================= Phase 4: G = Z2@W1b (->sx1), P0 = Z2@W0b (->U+0) =================
    {
        const float* z2s = U + 4608;
        float* P0 = U;
        for (int o = tid; o < 640; o += NTHREADS) {
            int k = o & 127, f = o >> 7;
            const float* zr  = &z2s[k * 36];
            const float* wp0 = &sw[768 + f * 32];
            const float* wp1 = &sw[928 + f * 32];
            ull g2a = 0ull, p2a = 0ull;
#pragma unroll
            for (int h = 0; h < 32; h += 4) {
                ulonglong2 zv  = *(const ulonglong2*)&zr[h];
                ulonglong2 w1v = *(const ulonglong2*)&wp1[h];
                ulonglong2 w0v = *(const ulonglong2*)&wp0[h];
                FMA2(g2a, zv.x, w1v.x);
                FMA2(g2a, zv.y, w1v.y);
                FMA2(p2a, zv.x, w0v.x);
                FMA2(p2a, zv.y, w0v.y);
            }
            sx1[f * 128 + k] = hadd2(g2a);
            P0[o] = hadd2(p2a);
        }
    }
    __syncthreads();

    // ================= Phase 5: partials of HW@G (j-split 2) =================
    {
        float* P5 = U + 640;
        const int k = tid & 127, q = tid >> 7;
        const int jb = 64 * q;
        const float* hr = &HWs[k * HWS + jb];
        ull a2[5] = {0ull, 0ull, 0ull, 0ull, 0ull};
#pragma unroll 4
        for (int j = 0; j < 64; j += 4) {
            ulonglong2 h2v = *(const ulonglong2*)&hr[j];
#pragma unroll
            for (int f = 0; f < 5; f++) {
                ulonglong2 gv = *(const ulonglong2*)&sx1[f * 128 + jb + j];
                FMA2(a2[f], h2v.x, gv.x);
                FMA2(a2[f], h2v.y, gv.y);
            }
        }
#pragma unroll
        for (int f = 0; f < 5; f++)
            P5[q * 640 + f * 128 + k] = hadd2(a2[f]);
    }
    __syncthreads();
    for (int o = tid; o < 640; o += NTHREADS)
        xs[o] += U[o] + U[640 + o] + U[1280 + o];
    __syncthreads();

    // ================= band-0 sum =================
    if (tid < 32) {
        float s = xs[tid] + xs[tid + 32] + xs[tid + 64] + xs[tid + 96];
#pragma unroll
        for (int m = 16; m > 0; m >>= 1) s += __shfl_xor_sync(0xffffffffu, s, m);
        if (tid == 0) red[0] = s;
    }
    __syncthreads();

    // ================= projection + band clamps =================
    {
        float fproj = red[0] - 10.0f;
        float nu3 = gnu3[0], tg = gtg[0];
        float Vnu = 1.f - 1.f / ((1.f + nu3) * (1.f + nu3));
        float Vg  = 1.f - 1.f / ((1.f + tg) * (1.f + tg));
        for (int m = tid; m < 640; m += NTHREADS) {
            float v = xs[m];
            int band = m >> 7;
            if (band == 0 && fproj > 0.f) v -= fproj * (1.f / 128.f);
            v = fmaxf(v, band == 1 ? nu3 : 0.f);
            if (band == 2) v = fminf(v, tg);
            if (band == 3) v = fminf(fmaxf(v, Vnu), Vg);
            xs[m] = v;
        }
    }
    __syncthreads();

    // ================= outputs =================
    {
        float* outx = out + (size_t)b * 640;
        for (int o = tid; o < 160; o += NTHREADS)
            *(float4*)&outx[o * 4] = *(const float4*)&xs[o * 4];
        float* dp = U + 1920;
        const int k = tid & 127, q = tid >> 7;
        float a = 0.f;
#pragma unroll 8
        for (int i = 64 * q; i < 64 * q + 64; i++)
            a += xs[i] * HWs[i * HWS + k];
        dp[q * 128 + k] = a;
    }
    __syncthreads();
    {
        const float* dp = U + 1920;
        const size_t BM = (size_t)Bsz * 640;
        const size_t BK = (size_t)Bsz * 128;
        if (tid < 128) {
            int k = tid;
            float p  = xs[k];
            float nu = xs[128 + k];
            float xg = xs[256 + k];
            float xv = xs[384 + k];
            float s4 = xs[512 + k];
            float f5 = 1.f - 1.f / ((1.f + xg) * (1.f + xg)) - xv;
            float f6 = sqrtf(xv) - s4;
            float dacc = dp[k] + dp[128 + k];
            float top  = p * HWs[k * HWS + k];
            float down = dacc - top + 1.f;
            out[BM +            (size_t)b * 128 + k] = f5;
            out[BM +     BK +   (size_t)b * 128 + k] = f6;
            out[BM + 2 * BK +   (size_t)b * 128 + k] = top - down * xg;
            out[BM + 3 * BK +   (size_t)b * 128 + k] = nu * down - top;
        }
    }
}

extern "C" void kernel_launch(void* const* d_in, const int* in_sizes, int n_in,
                              void* d_out, int out_size) {
    const float* HW    = (const float*)d_in[2];
    const float* x0    = (const float*)d_in[3];
    const float* nu3   = (const float*)d_in[4];
    const float* tg    = (const float*)d_in[5];
    const float* g1W0a = (const float*)d_in[12];
    const float* g1W1a = (const float*)d_in[13];
    const float* g1W0b = (const float*)d_in[14];
    const float* g1W1b = (const float*)d_in[15];
    const float* g2W0a = (const float*)d_in[16];
    const float* g2W1a = (const float*)d_in[17];
    const float* g2W0b = (const float*)d_in[18];
    const float* g2W1b = (const float*)d_in[19];

    cudaFuncSetAttribute(unfold_pocs_kernel,
                         cudaFuncAttributeMaxDynamicSharedMemorySize, SMEM_BYTES);

    unfold_pocs_kernel<<<Bsz, NTHREADS, SMEM_BYTES>>>(
        HW, x0, nu3, tg,
        g1W0a, g1W1a, g1W0b, g1W1b,
        g2W0a, g2W1a, g2W0b, g2W1b,
        (float*)d_out);
}

// round 10
// speedup vs baseline: 3.2449x; 1.2195x over previous
#include <cuda_runtime.h>
#include <math.h>
#include <stdint.h>

#define Bsz 2048
#define NTHREADS 256
#define HWS 132

typedef unsigned long long ull;

// ---- smem layout (float offsets) ----
#define O_HW   0        // 16896 : HW row-major stride 132
#define O_U    16896    // 9216 union region:
                        //  phase1: WBF (W64 frag) 8192 @ +0
                        //  GNN1 : scrZ (Z1, stride 33) 4224 @ +0 ; X1t frag 1024 @ +4352 ;
                        //          Wct frag 512 @ +5376 ; part 512 @ +5888
                        //  ph2/3: VBF frag 4096 @ +0 ; z2 [k][36] 4608 @ +4096
                        //  ph4/5: P0 640 @ +0 ; P5 1280 @ +640 ; dacc 256 @ +1920
#define O_XS   26112    // 640
#define O_SX1  26752    // 640 (later G)
#define O_SW   27392    // 1088
#define O_CC   28480    // 128
#define O_RED  28608    // 64
#define SMEM_FLOATS 28672
#define SMEM_BYTES (SMEM_FLOATS * 4)   // 114688 B -> 2 CTAs/SM

__device__ __forceinline__ ull dup2(float x) {
    ull r; asm("mov.b64 %0, {%1, %1};" : "=l"(r) : "f"(x)); return r;
}
#define FMA2(acc, a, b) asm("fma.rn.f32x2 %0, %1, %2, %0;" : "+l"(acc) : "l"(a), "l"(b))
__device__ __forceinline__ float hadd2(ull v) {
    float lo, hi; asm("mov.b64 {%0, %1}, %2;" : "=f"(lo), "=f"(hi) : "l"(v)); return lo + hi;
}
__device__ __forceinline__ void mma_tf32(float* c, const uint32_t* a, uint32_t b0, uint32_t b1) {
    asm volatile(
        "mma.sync.aligned.m16n8k8.row.col.f32.tf32.tf32.f32 "
        "{%0,%1,%2,%3}, {%4,%5,%6,%7}, {%8,%9}, {%0,%1,%2,%3};"
        : "+f"(c[0]), "+f"(c[1]), "+f"(c[2]), "+f"(c[3])
        : "r"(a[0]), "r"(a[1]), "r"(a[2]), "r"(a[3]), "r"(b0), "r"(b1));
}

__global__ __launch_bounds__(NTHREADS, 2)
void unfold_pocs_kernel(const float* __restrict__ gHW, const float* __restrict__ gx0,
                        const float* __restrict__ gnu3, const float* __restrict__ gtg,
                        const float* __restrict__ g1W0a, const float* __restrict__ g1W1a,
                        const float* __restrict__ g1W0b, const float* __restrict__ g1W1b,
                        const float* __restrict__ g2W0a, const float* __restrict__ g2W1a,
                        const float* __restrict__ g2W0b, const float* __restrict__ g2W1b,
                        float* __restrict__ out) {
    extern __shared__ float sm[];
    const int b = blockIdx.x;
    const int tid = threadIdx.x;
    const int wid = tid >> 5;
    const int lid = tid & 31;
    const int lr = lid >> 2;   // 0..7
    const int lc = lid & 3;    // 0..3

    float* HWs = sm + O_HW;
    float* U   = sm + O_U;
    float* xs  = sm + O_XS;
    float* sx1 = sm + O_SX1;
    float* sw  = sm + O_SW;
    float* cC  = sm + O_CC;
    float* red = sm + O_RED;

    const float* hwg = gHW + (size_t)b * (128 * 128);

    // ================= Phase 0: loads =================
    for (int o = tid; o < 4096; o += NTHREADS) {
        float4 v = *(const float4*)(hwg + o * 4);
        int w = o * 4;
        int row = w >> 7, col = w & 127;
        *(float4*)&HWs[row * HWS + col] = v;
    }
    for (int o = tid; o < 160; o += NTHREADS)
        *(float4*)&xs[o * 4] = *(const float4*)(gx0 + (size_t)b * 640 + o * 4);
    // W64 fragment-ordered into U+0 (vectorized gmem loads)
    {
        float* WBF = U;
        for (int o = tid; o < 1024; o += NTHREADS) {
            int k = o >> 3, h4 = (o & 7) * 4;
            float4 v0 = *(const float4*)&g2W0a[k * 32 + h4];
            float4 v1 = *(const float4*)&g2W1a[k * 32 + h4];
            int basek = (k >> 4) * 8;
            int comp  = (k >> 2) & 3;
            int l0    = (((h4 & 7) * 4 + (k & 3)) << 2) + comp;
            int c0 = (basek + (h4 >> 3)) << 7;       // W0a -> h = h4..h4+3
            int c1 = (basek + 4 + (h4 >> 3)) << 7;   // W1a -> h = 32+h4..
            WBF[c0 + l0]      = v0.x;
            WBF[c0 + l0 + 16] = v0.y;
            WBF[c0 + l0 + 32] = v0.z;
            WBF[c0 + l0 + 48] = v0.w;
            WBF[c1 + l0]      = v1.x;
            WBF[c1 + l0 + 16] = v1.y;
            WBF[c1 + l0 + 32] = v1.z;
            WBF[c1 + l0 + 48] = v1.w;
        }
    }
    for (int o = tid; o < 160; o += NTHREADS) sw[o]       = g1W0a[o];
    for (int o = tid; o < 160; o += NTHREADS) sw[160 + o] = g1W1a[o];
    for (int o = tid; o < 64;  o += NTHREADS) sw[320 + o] = g1W0b[o];
    for (int o = tid; o < 64;  o += NTHREADS) sw[384 + o] = g1W1b[o];
    for (int o = tid; o < 160; o += NTHREADS) sw[448 + o] = g2W0a[128 * 32 + o];
    for (int o = tid; o < 160; o += NTHREADS) sw[608 + o] = g2W1a[128 * 32 + o];
    for (int o = tid; o < 160; o += NTHREADS) {
        int f = o >> 5, h = o & 31;
        sw[768 + f * 32 + h] = g2W0b[h * 5 + f];
        sw[928 + f * 32 + h] = g2W1b[h * 5 + f];
    }
    __syncthreads();

    float acc[8][4];     // T fragments, then U0 in acc[0..3]
    float acc2[4][4];    // HW@V fragments
    const int m0 = wid * 16;

    // ================= Phase 1: T = HW @ W64 via HMMA tf32 =================
    {
        const float* WBF = U;
#pragma unroll
        for (int nt = 0; nt < 8; nt++)
#pragma unroll
            for (int c = 0; c < 4; c++) acc[nt][c] = 0.f;
#pragma unroll
        for (int kc = 0; kc < 8; kc++) {
            const int k0 = kc * 16;
            uint32_t a0[4], a1[4];
            a0[0] = __float_as_uint(HWs[(m0 + lr)     * HWS + k0 + lc]);
            a0[1] = __float_as_uint(HWs[(m0 + lr + 8) * HWS + k0 + lc]);
            a0[2] = __float_as_uint(HWs[(m0 + lr)     * HWS + k0 + lc + 4]);
            a0[3] = __float_as_uint(HWs[(m0 + lr + 8) * HWS + k0 + lc + 4]);
            a1[0] = __float_as_uint(HWs[(m0 + lr)     * HWS + k0 + 8 + lc]);
            a1[1] = __float_as_uint(HWs[(m0 + lr + 8) * HWS + k0 + 8 + lc]);
            a1[2] = __float_as_uint(HWs[(m0 + lr)     * HWS + k0 + 12 + lc]);
            a1[3] = __float_as_uint(HWs[(m0 + lr + 8) * HWS + k0 + 12 + lc]);
#pragma unroll
            for (int nt = 0; nt < 8; nt++) {
                float4 bv = *(const float4*)&WBF[((kc << 3) + nt) << 7 | (lid << 2)];
                mma_tf32(acc[nt], a0, __float_as_uint(bv.x), __float_as_uint(bv.y));
                mma_tf32(acc[nt], a1, __float_as_uint(bv.z), __float_as_uint(bv.w));
            }
        }
    }
    __syncthreads();   // WBF dead

    // ================= GNN1 (HMMA) =================
    {
        float* scrZ = U;          // Z1, stride 33
        float* X1t  = U + 4352;   // X1 frag (N=8)
        float* Wct  = U + 5376;   // cat-weights frag (k=16, N=32)
        float* part = U + 5888;

        // build X1t: B[k][f] = xs[f*128+k], f>=5 -> 0
        for (int o = tid; o < 1024; o += NTHREADS) {
            int k = o >> 3, f = o & 7;
            float v = (f < 5) ? xs[f * 128 + k] : 0.f;
            int pos = ((k >> 4) << 7) | ((f * 4 + (k & 3)) << 2) | ((k >> 2) & 3);
            X1t[pos] = v;
        }
        // build Wct: B[k][h], k<5 -> W0a[k][h], k<10 -> W1a[k-5][h], else 0
        for (int o = tid; o < 512; o += NTHREADS) {
            int h = o >> 4, k = o & 15;
            float v = (k < 5) ? sw[k * 32 + h] : (k < 10 ? sw[160 + (k - 5) * 32 + h] : 0.f);
            int pos = ((h >> 3) << 7) | (((h & 7) * 4 + (k & 3)) << 2) | ((k >> 2) & 3);
            Wct[pos] = v;
        }
        if (tid < 128) {
            float a = 0.f;
#pragma unroll 4
            for (int i = 0; i < 128; i++) a += HWs[i * HWS + tid];
            cC[tid] = a * (1.f / 128.f);
        }
        __syncthreads();

        // SX1 = HW @ X1 via HMMA (per warp: 16 rows)
        {
            float c[4] = {0.f, 0.f, 0.f, 0.f};
#pragma unroll
            for (int kc = 0; kc < 8; kc++) {
                const int k0 = kc * 16;
                uint32_t a0[4], a1[4];
                a0[0] = __float_as_uint(HWs[(m0 + lr)     * HWS + k0 + lc]);
                a0[1] = __float_as_uint(HWs[(m0 + lr + 8) * HWS + k0 + lc]);
                a0[2] = __float_as_uint(HWs[(m0 + lr)     * HWS + k0 + lc + 4]);
                a0[3] = __float_as_uint(HWs[(m0 + lr + 8) * HWS + k0 + lc + 4]);
                a1[0] = __float_as_uint(HWs[(m0 + lr)     * HWS + k0 + 8 + lc]);
                a1[1] = __float_as_uint(HWs[(m0 + lr + 8) * HWS + k0 + 8 + lc]);
                a1[2] = __float_as_uint(HWs[(m0 + lr)     * HWS + k0 + 12 + lc]);
                a1[3] = __float_as_uint(HWs[(m0 + lr + 8) * HWS + k0 + 12 + lc]);
                float4 bv = *(const float4*)&X1t[(kc << 7) | (lid << 2)];
                mma_tf32(c, a0, __float_as_uint(bv.x), __float_as_uint(bv.y));
                mma_tf32(c, a1, __float_as_uint(bv.z), __float_as_uint(bv.w));
            }
            int f0 = 2 * lc, f1 = 2 * lc + 1;
            if (f0 < 5) {
                sx1[f0 * 128 + m0 + lr]     = c[0];
                sx1[f0 * 128 + m0 + lr + 8] = c[2];
            }
            if (f1 < 5) {
                sx1[f1 * 128 + m0 + lr]     = c[1];
                sx1[f1 * 128 + m0 + lr + 8] = c[3];
            }
        }
        __syncthreads();

        // Z1 = relu(cat @ Wct) via HMMA, cat = [X1 | SX1] (k=10 pad 16)
        {
            const int row0 = m0 + lr, row1 = m0 + lr + 8;
            uint32_t a0[4], a1[4];
            a0[0] = __float_as_uint(xs[lc * 128 + row0]);
            a0[1] = __float_as_uint(xs[lc * 128 + row1]);
            a0[2] = __float_as_uint((lc == 0) ? xs[4 * 128 + row0] : sx1[(lc - 1) * 128 + row0]);
            a0[3] = __float_as_uint((lc == 0) ? xs[4 * 128 + row1] : sx1[(lc - 1) * 128 + row1]);
            a1[0] = (lc < 2) ? __float_as_uint(sx1[(lc + 3) * 128 + row0]) : 0u;
            a1[1] = (lc < 2) ? __float_as_uint(sx1[(lc + 3) * 128 + row1]) : 0u;
            a1[2] = 0u;
            a1[3] = 0u;
            float cz[4][4];
#pragma unroll
            for (int nt = 0; nt < 4; nt++) {
#pragma unroll
                for (int c = 0; c < 4; c++) cz[nt][c] = 0.f;
                float4 bv = *(const float4*)&Wct[(nt << 7) | (lid << 2)];
                mma_tf32(cz[nt], a0, __float_as_uint(bv.x), __float_as_uint(bv.y));
                mma_tf32(cz[nt], a1, __float_as_uint(bv.z), __float_as_uint(bv.w));
            }
#pragma unroll
            for (int nt = 0; nt < 4; nt++) {
                const int h0 = nt * 8 + 2 * lc;
                scrZ[row0 * 33 + h0]     = fmaxf(cz[nt][0], 0.f);
                scrZ[row0 * 33 + h0 + 1] = fmaxf(cz[nt][1], 0.f);
                scrZ[row1 * 33 + h0]     = fmaxf(cz[nt][2], 0.f);
                scrZ[row1 * 33 + h0 + 1] = fmaxf(cz[nt][3], 0.f);
            }
        }
        __syncthreads();

        // mean/cZ1 partials (256 threads)
        {
            const int h = tid & 31, q = tid >> 5;
            float m = 0.f, cz = 0.f;
#pragma unroll 4
            for (int k = q * 16; k < q * 16 + 16; k++) {
                float zv = scrZ[k * 33 + h];
                m += zv;
                cz += cC[k] * zv;
            }
            part[q * 32 + h] = m;
            part[256 + q * 32 + h] = cz;
        }
        __syncthreads();
        if (tid < 32) {
            float m = 0.f, cz = 0.f;
#pragma unroll
            for (int q = 0; q < 8; q++) {
                m  += part[q * 32 + tid];
                cz += part[256 + q * 32 + tid];
            }
            red[tid] = m * (1.f / 128.f);
            red[32 + tid] = cz;
        }
        __syncthreads();
        if (tid < 2) {
            const float* w0b = sw + 320;
            const float* w1b = sw + 384;
            float a = 0.f;
#pragma unroll 8
            for (int h = 0; h < 32; h++)
                a += red[h] * w0b[h * 2 + tid] + red[32 + h] * w1b[h * 2 + tid];
            red[62 + tid] = fmaxf(a, 0.f);   // lbd
        }
        __syncthreads();
        if (tid < 128) {
            float l0 = red[62], l1 = red[63];
            float s1v = xs[128 + tid];
            xs[128 + tid] = s1v - l0 * ((1.0f / 128.f) / (1.f + s1v));
            xs[512 + tid] += l1 * ((1.0f / 128.f) * 0.1f);
        }
    }
    __syncthreads();   // xs final

    // ================= Phase 2+3: U0 in regs, V frag, HMMA HW@V, z2 =================
    {
        float* VBF = U;            // V fragment order (N=32 -> NT8=4)
        float* z2s = U + 4096;     // [k][36]
        const float* w0bot = sw + 448;
        const float* w1bot = sw + 608;
        float xr[2][5];
#pragma unroll
        for (int f = 0; f < 5; f++) {
            xr[0][f] = xs[f * 128 + m0 + lr];
            xr[1][f] = xs[f * 128 + m0 + lr + 8];
        }
        const int lr3 = lr & 3, lrh = lr >> 2;
#pragma unroll
        for (int nt = 0; nt < 8; nt++) {
            const bool isU = nt < 4;
            const float* wb = isU ? w0bot : w1bot;
            const int hb = (isU ? nt : nt - 4) * 8 + 2 * lc;
            float r00 = acc[nt][0], r01 = acc[nt][1];
            float r10 = acc[nt][2], r11 = acc[nt][3];
#pragma unroll
            for (int f = 0; f < 5; f++) {
                float w0 = wb[f * 32 + hb], w1 = wb[f * 32 + hb + 1];
                r00 += xr[0][f] * w0; r01 += xr[0][f] * w1;
                r10 += xr[1][f] * w0; r11 += xr[1][f] * w1;
            }
            if (isU) {
                acc[nt][0] = r00; acc[nt][1] = r01; acc[nt][2] = r10; acc[nt][3] = r11;
            } else {
                // frag store: rows m0+lr (comp lrh), m0+lr+8 (comp 2+lrh); h = hb, hb+1
                const int ch = ((wid * 4) + (nt - 4)) << 7;
                const int p0 = ch | (((2 * lc) * 4 + lr3) << 2);
                const int p1 = ch | (((2 * lc + 1) * 4 + lr3) << 2);
                VBF[p0 + lrh]     = r00;
                VBF[p1 + lrh]     = r01;
                VBF[p0 + 2 + lrh] = r10;
                VBF[p1 + 2 + lrh] = r11;
            }
        }
        __syncthreads();   // V fully written

        // HW @ V full-K via HMMA, frag B
#pragma unroll
        for (int nt = 0; nt < 4; nt++)
#pragma unroll
            for (int c = 0; c < 4; c++) acc2[nt][c] = 0.f;
#pragma unroll
        for (int kc = 0; kc < 8; kc++) {
            const int k0 = kc * 16;
            uint32_t a0[4], a1[4];
            a0[0] = __float_as_uint(HWs[(m0 + lr)     * HWS + k0 + lc]);
            a0[1] = __float_as_uint(HWs[(m0 + lr + 8) * HWS + k0 + lc]);
            a0[2] = __float_as_uint(HWs[(m0 + lr)     * HWS + k0 + lc + 4]);
            a0[3] = __float_as_uint(HWs[(m0 + lr + 8) * HWS + k0 + lc + 4]);
            a1[0] = __float_as_uint(HWs[(m0 + lr)     * HWS + k0 + 8 + lc]);
            a1[1] = __float_as_uint(HWs[(m0 + lr + 8) * HWS + k0 + 8 + lc]);
            a1[2] = __float_as_uint(HWs[(m0 + lr)     * HWS + k0 + 12 + lc]);
            a1[3] = __float_as_uint(HWs[(m0 + lr + 8) * HWS + k0 + 12 + lc]);
#pragma unroll
            for (int nt = 0; nt < 4; nt++) {
                float4 bv = *(const float4*)&VBF[((kc << 2) + nt) << 7 | (lid << 2)];
                mma_tf32(acc2[nt], a0, __float_as_uint(bv.x), __float_as_uint(bv.y));
                mma_tf32(acc2[nt], a1, __float_as_uint(bv.z), __float_as_uint(bv.w));
            }
        }
        // z2 = relu(U0 + HW@V)
#pragma unroll
        for (int nt = 0; nt < 4; nt++) {
            const int hb = nt * 8 + 2 * lc;
            *(float2*)&z2s[(m0 + lr) * 36 + hb] =
                make_float2(fmaxf(acc[nt][0] + acc2[nt][0], 0.f),
                            fmaxf(acc[nt][1] + acc2[nt][1], 0.f));
            *(float2*)&z2s[(m0 + lr + 8) * 36 + hb] =
                make_float2(fmaxf(acc[nt][2] + acc2[nt][2], 0.f),
                            fmaxf(acc[nt][3] + acc2[nt][3], 0.f));
        }
    }
    __syncthreads();

    // ================= Phase 4: G = Z2@W1b (->sx1), P0 = Z2@W0b (->U+0) =================
    {
        const float* z2s = U + 4096;
        float* P0 = U;
        for (int o = tid; o < 640; o += NTHREADS) {
            int k = o & 127, f = o >> 7;
            const float* zr  = &z2s[k * 36];
            const float* wp0 = &sw[768 + f * 32];
            const float* wp1 = &sw[928 + f * 32];
            ull g2a = 0ull, p2a = 0ull;
#pragma unroll
            for (int h = 0; h < 32; h += 4) {
                ulonglong2 zv  = *(const ulonglong2*)&zr[h];
                ulonglong2 w1v = *(const ulonglong2*)&wp1[h];
                ulonglong2 w0v = *(const ulonglong2*)&wp0[h];
                FMA2(g2a, zv.x, w1v.x);
                FMA2(g2a, zv.y, w1v.y);
                FMA2(p2a, zv.x, w0v.x);
                FMA2(p2a, zv.y, w0v.y);
            }
            sx1[f * 128 + k] = hadd2(g2a);
            P0[o] = hadd2(p2a);
        }
    }
    __syncthreads();

    // ================= Phase 5: partials of HW@G (j-split 2) =================
    {
        float* P5 = U + 640;
        const int k = tid & 127, q = tid >> 7;
        const int jb = 64 * q;
        const float* hr = &HWs[k * HWS + jb];
        ull a2[5] = {0ull, 0ull, 0ull, 0ull, 0ull};
#pragma unroll 4
        for (int j = 0; j < 64; j += 4) {
            ulonglong2 h2v = *(const ulonglong2*)&hr[j];
#pragma unroll
            for (int f = 0; f < 5; f++) {
                ulonglong2 gv = *(const ulonglong2*)&sx1[f * 128 + jb + j];
                FMA2(a2[f], h2v.x, gv.x);
                FMA2(a2[f], h2v.y, gv.y);
            }
        }
#pragma unroll
        for (int f = 0; f < 5; f++)
            P5[q * 640 + f * 128 + k] = hadd2(a2[f]);
    }
    __syncthreads();
    for (int o = tid; o < 640; o += NTHREADS)
        xs[o] += U[o] + U[640 + o] + U[1280 + o];
    __syncthreads();

    // ================= band-0 sum =================
    if (tid < 32) {
        float s = xs[tid] + xs[tid + 32] + xs[tid + 64] + xs[tid + 96];
#pragma unroll
        for (int m = 16; m > 0; m >>= 1) s += __shfl_xor_sync(0xffffffffu, s, m);
        if (tid == 0) red[0] = s;
    }
    __syncthreads();

    // ================= projection + band clamps =================
    {
        float fproj = red[0] - 10.0f;
        float nu3 = gnu3[0], tg = gtg[0];
        float Vnu = 1.f - 1.f / ((1.f + nu3) * (1.f + nu3));
        float Vg  = 1.f - 1.f / ((1.f + tg) * (1.f + tg));
        for (int m = tid; m < 640; m += NTHREADS) {
            float v = xs[m];
            int band = m >> 7;
            if (band == 0 && fproj > 0.f) v -= fproj * (1.f / 128.f);
            v = fmaxf(v, band == 1 ? nu3 : 0.f);
            if (band == 2) v = fminf(v, tg);
            if (band == 3) v = fminf(fmaxf(v, Vnu), Vg);
            xs[m] = v;
        }
    }
    __syncthreads();

    // ================= outputs =================
    {
        float* outx = out + (size_t)b * 640;
        for (int o = tid; o < 160; o += NTHREADS)
            *(float4*)&outx[o * 4] = *(const float4*)&xs[o * 4];
        float* dp = U + 1920;
        const int k = tid & 127, q = tid >> 7;
        float a = 0.f;
#pragma unroll 8
        for (int i = 64 * q; i < 64 * q + 64; i++)
            a += xs[i] * HWs[i * HWS + k];
        dp[q * 128 + k] = a;
    }
    __syncthreads();
    {
        const float* dp = U + 1920;
        const size_t BM = (size_t)Bsz * 640;
        const size_t BK = (size_t)Bsz * 128;
        if (tid < 128) {
            int k = tid;
            float p  = xs[k];
            float nu = xs[128 + k];
            float xg = xs[256 + k];
            float xv = xs[384 + k];
            float s4 = xs[512 + k];
            float f5 = 1.f - 1.f / ((1.f + xg) * (1.f + xg)) - xv;
            float f6 = sqrtf(xv) - s4;
            float dacc = dp[k] + dp[128 + k];
            float top  = p * HWs[k * HWS + k];
            float down = dacc - top + 1.f;
            out[BM +            (size_t)b * 128 + k] = f5;
            out[BM +     BK +   (size_t)b * 128 + k] = f6;
            out[BM + 2 * BK +   (size_t)b * 128 + k] = top - down * xg;
            out[BM + 3 * BK +   (size_t)b * 128 + k] = nu * down - top;
        }
    }
}

extern "C" void kernel_launch(void* const* d_in, const int* in_sizes, int n_in,
                              void* d_out, int out_size) {
    const float* HW    = (const float*)d_in[2];
    const float* x0    = (const float*)d_in[3];
    const float* nu3   = (const float*)d_in[4];
    const float* tg    = (const float*)d_in[5];
    const float* g1W0a = (const float*)d_in[12];
    const float* g1W1a = (const float*)d_in[13];
    const float* g1W0b = (const float*)d_in[14];
    const float* g1W1b = (const float*)d_in[15];
    const float* g2W0a = (const float*)d_in[16];
    const float* g2W1a = (const float*)d_in[17];
    const float* g2W0b = (const float*)d_in[18];
    const float* g2W1b = (const float*)d_in[19];

    cudaFuncSetAttribute(unfold_pocs_kernel,
                         cudaFuncAttributeMaxDynamicSharedMemorySize, SMEM_BYTES);

    unfold_pocs_kernel<<<Bsz, NTHREADS, SMEM_BYTES>>>(
        HW, x0, nu3, tg,
        g1W0a, g1W1a, g1W0b, g1W1b,
        g2W0a, g2W1a, g2W0b, g2W1b,
        (float*)d_out);
}